// round 10
// baseline (speedup 1.0000x reference)
#include <cuda_runtime.h>
#include <cstdint>

#define NDRUG 100000
#define NSIDE 5000
#define FDIM  128
#define EMAX  1000000

// ---------------------------------------------------------------------------
// Static device scratch
// ---------------------------------------------------------------------------
__device__ __align__(16) float g_rs_r_src[NDRUG];
__device__ __align__(16) float g_rs_r_dst[NSIDE];
__device__ __align__(16) float g_rs_s_src[NDRUG];
__device__ __align__(16) float g_rs_s_dst[NDRUG];

__device__ __align__(16) float g_hd_a[NDRUG * FDIM];
__device__ __align__(16) float g_hd_b[NDRUG * FDIM];
__device__ __align__(16) float g_hs_a[NSIDE * FDIM];
__device__ __align__(16) float g_hs_b[NSIDE * FDIM];

// Projected per-relation features, stored as packed f16x2 words
// (halves gather traffic vs fp32). Row = NOUT/2 words.
__device__ __align__(16) uint32_t g_y_rel[NDRUG * FDIM / 2];
__device__ __align__(16) uint32_t g_y_relby[NSIDE * FDIM / 2];
__device__ __align__(16) uint32_t g_y_sim[NDRUG * FDIM / 2];
__device__ __align__(16) uint32_t g_y_simby[NDRUG * FDIM / 2];

// CSR: A by relate_dst(side)<-relate_src ; B by relate_src(drug)<-relate_dst ;
//      C by sim_dst(drug)<-sim_src ; D by sim_src(drug)<-sim_dst
__device__ __align__(16) int g_cntA[NSIDE], g_offA[NSIDE], g_curA[NSIDE];
__device__ __align__(16) int g_cntB[NDRUG], g_offB[NDRUG], g_curB[NDRUG];
__device__ __align__(16) int g_cntC[NDRUG], g_offC[NDRUG], g_curC[NDRUG];
__device__ __align__(16) int g_cntD[NDRUG], g_offD[NDRUG], g_curD[NDRUG];
__device__ __align__(16) int g_idxA[EMAX], g_idxB[EMAX], g_idxC[EMAX], g_idxD[EMAX];

// ---------------------------------------------------------------------------
// f16x2 helpers via inline PTX
// ---------------------------------------------------------------------------
__device__ __forceinline__ uint32_t pack_h2(float lo, float hi) {
    uint32_t r;
    asm("cvt.rn.f16x2.f32 %0, %1, %2;" : "=r"(r) : "f"(hi), "f"(lo));
    return r;
}
__device__ __forceinline__ float2 unpack_h2(uint32_t v) {
    float2 f;
    asm("{ .reg .f16 lo, hi;\n\t"
        "  mov.b32 {lo, hi}, %2;\n\t"
        "  cvt.f32.f16 %0, lo;\n\t"
        "  cvt.f32.f16 %1, hi; }"
        : "=f"(f.x), "=f"(f.y) : "r"(v));
    return f;
}

// ---------------------------------------------------------------------------
// Utility kernels
// ---------------------------------------------------------------------------
__global__ void zero_cnts(int4* __restrict__ a, int4* __restrict__ b,
                          int4* __restrict__ c, int4* __restrict__ d) {
    int i = blockIdx.x * blockDim.x + threadIdx.x;
    int4 z = make_int4(0, 0, 0, 0);
    if (i < NSIDE / 4) a[i] = z;
    if (i < NDRUG / 4) { b[i] = z; c[i] = z; d[i] = z; }
}

__global__ void hist_kernel(const int* __restrict__ rsrc, const int* __restrict__ rdst,
                            const int* __restrict__ ssrc, const int* __restrict__ sdst,
                            int Er, int Es,
                            int* __restrict__ cA, int* __restrict__ cB,
                            int* __restrict__ cC, int* __restrict__ cD) {
    int e = blockIdx.x * blockDim.x + threadIdx.x;
    if (e < Er) {
        atomicAdd(&cA[rdst[e]], 1);
        atomicAdd(&cB[rsrc[e]], 1);
    }
    if (e < Es) {
        atomicAdd(&cC[sdst[e]], 1);
        atomicAdd(&cD[ssrc[e]], 1);
    }
}

__global__ void scan4(const int* __restrict__ cA, const int* __restrict__ cB,
                      const int* __restrict__ cC, const int* __restrict__ cD,
                      int* __restrict__ offA, int* __restrict__ curA, float* __restrict__ rsA,
                      int* __restrict__ offB, int* __restrict__ curB, float* __restrict__ rsB,
                      int* __restrict__ offC, int* __restrict__ curC, float* __restrict__ rsC,
                      int* __restrict__ offD, int* __restrict__ curD, float* __restrict__ rsD) {
    __shared__ int sm[1024];
    int b = blockIdx.x, tid = threadIdx.x;
    const int* cnt; int* off; int* cur; float* rs; int n;
    if (b == 0)      { cnt = cA; off = offA; cur = curA; rs = rsA; n = NSIDE; }
    else if (b == 1) { cnt = cB; off = offB; cur = curB; rs = rsB; n = NDRUG; }
    else if (b == 2) { cnt = cC; off = offC; cur = curC; rs = rsC; n = NDRUG; }
    else             { cnt = cD; off = offD; cur = curD; rs = rsD; n = NDRUG; }

    int chunk = (n + 1023) >> 10;
    int s0 = tid * chunk;
    int s1 = min(s0 + chunk, n);
    int s = 0;
    for (int i = s0; i < s1; ++i) s += cnt[i];
    sm[tid] = s;
    __syncthreads();
    for (int d = 1; d < 1024; d <<= 1) {
        int x = (tid >= d) ? sm[tid - d] : 0;
        __syncthreads();
        sm[tid] += x;
        __syncthreads();
    }
    int run = sm[tid] - s;  // exclusive prefix
    for (int i = s0; i < s1; ++i) {
        int c = cnt[i];
        off[i] = run;
        cur[i] = run;
        rs[i] = rsqrtf((float)(c > 0 ? c : 1));
        run += c;
    }
}

__global__ void fill_all(const int* __restrict__ rsrc, const int* __restrict__ rdst,
                         const int* __restrict__ ssrc, const int* __restrict__ sdst,
                         int Er, int Es,
                         int* __restrict__ curA, int* __restrict__ idxA,
                         int* __restrict__ curB, int* __restrict__ idxB,
                         int* __restrict__ curC, int* __restrict__ idxC,
                         int* __restrict__ curD, int* __restrict__ idxD) {
    int e = blockIdx.x * blockDim.x + threadIdx.x;
    if (e < Er) {
        int s = rsrc[e], d = rdst[e];
        idxA[atomicAdd(&curA[d], 1)] = s;
        idxB[atomicAdd(&curB[s], 1)] = d;
    }
    if (e < Es) {
        int s = ssrc[e], d = sdst[e];
        idxC[atomicAdd(&curC[d], 1)] = s;
        idxD[atomicAdd(&curD[s], 1)] = d;
    }
}

// ---------------------------------------------------------------------------
// tf32 tensor-core multi-relation GEMM, f16x2-packed output (round-9 proven).
// ---------------------------------------------------------------------------
__device__ __forceinline__ uint32_t f2tf(float f) {
    uint32_t r;
    asm("cvt.rna.tf32.f32 %0, %1;" : "=r"(r) : "f"(f));
    return r;
}
__device__ __forceinline__ void mma_tf32(float* d, const uint32_t* a, uint32_t b0, uint32_t b1) {
    asm("mma.sync.aligned.m16n8k8.row.col.f32.tf32.tf32.f32 "
        "{%0,%1,%2,%3}, {%4,%5,%6,%7}, {%8,%9}, {%0,%1,%2,%3};"
        : "+f"(d[0]), "+f"(d[1]), "+f"(d[2]), "+f"(d[3])
        : "r"(a[0]), "r"(a[1]), "r"(a[2]), "r"(a[3]), "r"(b0), "r"(b1));
}

template <int NOUT, int NREL>
__global__ __launch_bounds__(256) void gemm_tf32_multi(
    const float* __restrict__ X, int n,
    const float* __restrict__ W0, const float* __restrict__ W1, const float* __restrict__ W2,
    const float* __restrict__ rs0, const float* __restrict__ rs1, const float* __restrict__ rs2,
    uint32_t* __restrict__ Y0, uint32_t* __restrict__ Y1, uint32_t* __restrict__ Y2) {
    constexpr int XP = 132;
    constexpr int WP = NOUT + 8;
    constexpr int WN = NOUT / 4;
    constexpr int NT = WN / 8;
    constexpr int YW = NOUT / 2;

    extern __shared__ uint32_t smu[];
    uint32_t* Xs = smu;            // 64 * XP
    uint32_t* Ws = smu + 64 * XP;  // 128 * WP

    const int tid = threadIdx.x;
    const int row0 = blockIdx.x * 64;

    for (int i = tid; i < 64 * 32; i += 256) {
        int r = i >> 5, c4 = i & 31;
        int row = row0 + r;
        float4 v = make_float4(0.f, 0.f, 0.f, 0.f);
        if (row < n) v = reinterpret_cast<const float4*>(X)[row * 32 + c4];
        uint4 u = make_uint4(f2tf(v.x), f2tf(v.y), f2tf(v.z), f2tf(v.w));
        *reinterpret_cast<uint4*>(&Xs[r * XP + c4 * 4]) = u;
    }

    const int lane = tid & 31, wid = tid >> 5;
    const int g = lane >> 2, t = lane & 3;
    const int wm = wid & 1, wn = wid >> 1;
    const int nbase = wn * WN;
    const uint32_t* xbase = Xs + (wm * 32) * XP;

    #pragma unroll
    for (int rel = 0; rel < NREL; ++rel) {
        const float* W  = (rel == 0) ? W0  : (rel == 1) ? W1  : W2;
        const float* rs = (rel == 0) ? rs0 : (rel == 1) ? rs1 : rs2;
        uint32_t* Y     = (rel == 0) ? Y0  : (rel == 1) ? Y1  : Y2;

        __syncthreads();
        for (int i = tid; i < 128 * (NOUT / 4); i += 256) {
            int k = i / (NOUT / 4), c4 = i % (NOUT / 4);
            float4 v = reinterpret_cast<const float4*>(W)[i];
            uint4 u = make_uint4(f2tf(v.x), f2tf(v.y), f2tf(v.z), f2tf(v.w));
            *reinterpret_cast<uint4*>(&Ws[k * WP + c4 * 4]) = u;
        }
        __syncthreads();

        float acc[2][NT][4];
        #pragma unroll
        for (int mi = 0; mi < 2; ++mi)
            #pragma unroll
            for (int ni = 0; ni < NT; ++ni)
                #pragma unroll
                for (int j = 0; j < 4; ++j) acc[mi][ni][j] = 0.f;

        #pragma unroll
        for (int ks = 0; ks < 16; ++ks) {
            const int k0 = ks * 8;
            uint32_t a[2][4];
            #pragma unroll
            for (int mi = 0; mi < 2; ++mi) {
                const uint32_t* xb = xbase + mi * 16 * XP + k0;
                a[mi][0] = xb[g * XP + t];
                a[mi][1] = xb[(g + 8) * XP + t];
                a[mi][2] = xb[g * XP + t + 4];
                a[mi][3] = xb[(g + 8) * XP + t + 4];
            }
            #pragma unroll
            for (int ni = 0; ni < NT; ++ni) {
                uint32_t b0 = Ws[(k0 + t) * WP + nbase + ni * 8 + g];
                uint32_t b1 = Ws[(k0 + t + 4) * WP + nbase + ni * 8 + g];
                #pragma unroll
                for (int mi = 0; mi < 2; ++mi) mma_tf32(acc[mi][ni], a[mi], b0, b1);
            }
        }

        #pragma unroll
        for (int mi = 0; mi < 2; ++mi) {
            int r0 = row0 + wm * 32 + mi * 16 + g;
            float sa = (r0 < n) ? rs[r0] : 0.f;
            float sb = (r0 + 8 < n) ? rs[r0 + 8] : 0.f;
            #pragma unroll
            for (int ni = 0; ni < NT; ++ni) {
                int colw = (nbase + ni * 8 + 2 * t) >> 1;
                if (r0 < n)
                    Y[(long long)r0 * YW + colw] =
                        pack_h2(acc[mi][ni][0] * sa, acc[mi][ni][1] * sa);
                if (r0 + 8 < n)
                    Y[(long long)(r0 + 8) * YW + colw] =
                        pack_h2(acc[mi][ni][2] * sb, acc[mi][ni][3] * sb);
            }
        }
    }
}

// ---------------------------------------------------------------------------
// Merged CSR gather over f16x2 Y. One warp per dst row; fp32 accumulation.
// Inner loop: fixed-unroll batches of 8 PREDICATED row loads -> MLP=8
// regardless of degree (invalid slots load-disabled, zero-filled).
// ---------------------------------------------------------------------------
// NOUT=128: row = 32 uint2 (256B); lane covers cols [4*lane, 4*lane+4)
__device__ __forceinline__ float4 segsum4h(const uint2* __restrict__ Y, int beg, int m,
                                           const int* __restrict__ idx, int lane) {
    float4 acc = make_float4(0.f, 0.f, 0.f, 0.f);
    for (int e0 = 0; e0 < m; e0 += 32) {
        int lim = min(32, m - e0);
        int myi = (lane < lim) ? idx[beg + e0 + lane] : 0;
        for (int jb = 0; jb < lim; jb += 8) {
            uint2 v[8];
            #pragma unroll
            for (int j = 0; j < 8; ++j) {
                int s = __shfl_sync(0xffffffffu, myi, jb + j);
                v[j] = (jb + j < lim) ? Y[s * 32 + lane] : make_uint2(0u, 0u);
            }
            #pragma unroll
            for (int j = 0; j < 8; ++j) {
                float2 f0 = unpack_h2(v[j].x);
                float2 f1 = unpack_h2(v[j].y);
                acc.x += f0.x; acc.y += f0.y; acc.z += f1.x; acc.w += f1.y;
            }
        }
    }
    return acc;
}
// NOUT=64: row = 32 words (128B); lane covers cols [2*lane, 2*lane+2)
__device__ __forceinline__ float2 segsum2h(const uint32_t* __restrict__ Y, int beg, int m,
                                           const int* __restrict__ idx, int lane) {
    float2 acc = make_float2(0.f, 0.f);
    for (int e0 = 0; e0 < m; e0 += 32) {
        int lim = min(32, m - e0);
        int myi = (lane < lim) ? idx[beg + e0 + lane] : 0;
        for (int jb = 0; jb < lim; jb += 8) {
            uint32_t v[8];
            #pragma unroll
            for (int j = 0; j < 8; ++j) {
                int s = __shfl_sync(0xffffffffu, myi, jb + j);
                v[j] = (jb + j < lim) ? Y[s * 32 + lane] : 0u;
            }
            #pragma unroll
            for (int j = 0; j < 8; ++j) {
                float2 f = unpack_h2(v[j]);
                acc.x += f.x; acc.y += f.y;
            }
        }
    }
    return acc;
}

template <int NOUT>
__global__ __launch_bounds__(256) void gather_all(
    const uint32_t* __restrict__ yA, const int* __restrict__ offA, const int* __restrict__ cntA,
    const int* __restrict__ idxA, const float* __restrict__ rsA,
    const uint32_t* __restrict__ yB, const int* __restrict__ offB, const int* __restrict__ cntB,
    const int* __restrict__ idxB, const float* __restrict__ rsB,
    const uint32_t* __restrict__ yC, const int* __restrict__ offC, const int* __restrict__ cntC,
    const int* __restrict__ idxC, const float* __restrict__ rsC,
    const uint32_t* __restrict__ yD, const int* __restrict__ offD, const int* __restrict__ cntD,
    const int* __restrict__ idxD, const float* __restrict__ rsD,
    const float* __restrict__ b, float* __restrict__ out_side, float* __restrict__ out_drug,
    int relu) {
    int w = (blockIdx.x * blockDim.x + threadIdx.x) >> 5;
    int lane = threadIdx.x & 31;

    if (w < NSIDE) {
        float s = rsA[w];
        if constexpr (NOUT == 128) {
            float4 a = segsum4h(reinterpret_cast<const uint2*>(yA), offA[w], cntA[w], idxA, lane);
            float4 bb = reinterpret_cast<const float4*>(b)[lane];
            float4 v = make_float4(fmaf(a.x, s, bb.x), fmaf(a.y, s, bb.y),
                                   fmaf(a.z, s, bb.z), fmaf(a.w, s, bb.w));
            if (relu) { v.x = fmaxf(v.x, 0.f); v.y = fmaxf(v.y, 0.f); v.z = fmaxf(v.z, 0.f); v.w = fmaxf(v.w, 0.f); }
            reinterpret_cast<float4*>(out_side)[w * 32 + lane] = v;
        } else {
            float2 a = segsum2h(yA, offA[w], cntA[w], idxA, lane);
            float2 bb = reinterpret_cast<const float2*>(b)[lane];
            float2 v = make_float2(fmaf(a.x, s, bb.x), fmaf(a.y, s, bb.y));
            if (relu) { v.x = fmaxf(v.x, 0.f); v.y = fmaxf(v.y, 0.f); }
            reinterpret_cast<float2*>(out_side)[w * 32 + lane] = v;
        }
        return;
    }
    int d = w - NSIDE;
    if (d >= NDRUG) return;
    float s1 = rsB[d], s2 = rsC[d], s3 = rsD[d];
    if constexpr (NOUT == 128) {
        float4 a1 = segsum4h(reinterpret_cast<const uint2*>(yB), offB[d], cntB[d], idxB, lane);
        float4 a2 = segsum4h(reinterpret_cast<const uint2*>(yC), offC[d], cntC[d], idxC, lane);
        float4 a3 = segsum4h(reinterpret_cast<const uint2*>(yD), offD[d], cntD[d], idxD, lane);
        float4 b1 = reinterpret_cast<const float4*>(b)[1 * 32 + lane];
        float4 b2 = reinterpret_cast<const float4*>(b)[2 * 32 + lane];
        float4 b3 = reinterpret_cast<const float4*>(b)[3 * 32 + lane];
        float4 v;
        v.x = fmaf(a1.x, s1, b1.x) + fmaf(a2.x, s2, b2.x) + fmaf(a3.x, s3, b3.x);
        v.y = fmaf(a1.y, s1, b1.y) + fmaf(a2.y, s2, b2.y) + fmaf(a3.y, s3, b3.y);
        v.z = fmaf(a1.z, s1, b1.z) + fmaf(a2.z, s2, b2.z) + fmaf(a3.z, s3, b3.z);
        v.w = fmaf(a1.w, s1, b1.w) + fmaf(a2.w, s2, b2.w) + fmaf(a3.w, s3, b3.w);
        if (relu) { v.x = fmaxf(v.x, 0.f); v.y = fmaxf(v.y, 0.f); v.z = fmaxf(v.z, 0.f); v.w = fmaxf(v.w, 0.f); }
        reinterpret_cast<float4*>(out_drug)[d * 32 + lane] = v;
    } else {
        float2 a1 = segsum2h(yB, offB[d], cntB[d], idxB, lane);
        float2 a2 = segsum2h(yC, offC[d], cntC[d], idxC, lane);
        float2 a3 = segsum2h(yD, offD[d], cntD[d], idxD, lane);
        float2 b1 = reinterpret_cast<const float2*>(b)[1 * 32 + lane];
        float2 b2 = reinterpret_cast<const float2*>(b)[2 * 32 + lane];
        float2 b3 = reinterpret_cast<const float2*>(b)[3 * 32 + lane];
        float2 v;
        v.x = fmaf(a1.x, s1, b1.x) + fmaf(a2.x, s2, b2.x) + fmaf(a3.x, s3, b3.x);
        v.y = fmaf(a1.y, s1, b1.y) + fmaf(a2.y, s2, b2.y) + fmaf(a3.y, s3, b3.y);
        if (relu) { v.x = fmaxf(v.x, 0.f); v.y = fmaxf(v.y, 0.f); }
        reinterpret_cast<float2*>(out_drug)[d * 32 + lane] = v;
    }
}

// ---------------------------------------------------------------------------
// Host side
// ---------------------------------------------------------------------------
struct Scratch {
    float *rs_r_src, *rs_r_dst, *rs_s_src, *rs_s_dst;
    float *hd_a, *hd_b, *hs_a, *hs_b;
    uint32_t *y_rel, *y_relby, *y_sim, *y_simby;
    int *cntA, *offA, *curA, *idxA;
    int *cntB, *offB, *curB, *idxB;
    int *cntC, *offC, *curC, *idxC;
    int *cntD, *offD, *curD, *idxD;
};

static inline int cdiv(long long a, long long b) { return (int)((a + b - 1) / b); }

template <int NOUT>
static void run_layer(const Scratch& S,
                      const float* hd_in, const float* hs_in,
                      float* hd_out, float* hs_out,
                      const float* W, const float* b, int relu) {
    constexpr int XP = 132, WP = NOUT + 8;
    const int smem = (64 * XP + 128 * WP) * 4;
    const long long ws = 128LL * NOUT;

    gemm_tf32_multi<NOUT, 3><<<cdiv(NDRUG, 64), 256, smem>>>(
        hd_in, NDRUG,
        W + 0 * ws, W + 2 * ws, W + 3 * ws,
        S.rs_r_src, S.rs_s_src, S.rs_s_dst,
        S.y_rel, S.y_sim, S.y_simby);
    gemm_tf32_multi<NOUT, 1><<<cdiv(NSIDE, 64), 256, smem>>>(
        hs_in, NSIDE,
        W + 1 * ws, W + 1 * ws, W + 1 * ws,
        S.rs_r_dst, S.rs_r_dst, S.rs_r_dst,
        S.y_relby, S.y_relby, S.y_relby);

    gather_all<NOUT><<<cdiv((NDRUG + NSIDE) * 32, 256), 256>>>(
        S.y_rel, S.offA, S.cntA, S.idxA, S.rs_r_dst,
        S.y_relby, S.offB, S.cntB, S.idxB, S.rs_r_src,
        S.y_sim,   S.offC, S.cntC, S.idxC, S.rs_s_dst,
        S.y_simby, S.offD, S.cntD, S.idxD, S.rs_s_src,
        b, hs_out, hd_out, relu);
}

extern "C" void kernel_launch(void* const* d_in, const int* in_sizes, int n_in,
                              void* d_out, int out_size) {
    const float* embed_drug = (const float*)d_in[0];
    const float* embed_side = (const float*)d_in[1];
    const int* rsrc = (const int*)d_in[2];
    const int* rdst = (const int*)d_in[3];
    const int* ssrc = (const int*)d_in[4];
    const int* sdst = (const int*)d_in[5];
    const float* W1 = (const float*)d_in[6];
    const float* b1 = (const float*)d_in[7];
    const float* W2 = (const float*)d_in[8];
    const float* b2 = (const float*)d_in[9];
    const float* W3 = (const float*)d_in[10];
    const float* b3 = (const float*)d_in[11];
    const int Er = in_sizes[2];
    const int Es = in_sizes[4];

    const int sm128 = (64 * 132 + 128 * 136) * 4;
    const int sm64  = (64 * 132 + 128 * 72) * 4;
    cudaFuncSetAttribute(gemm_tf32_multi<128, 3>, cudaFuncAttributeMaxDynamicSharedMemorySize, sm128);
    cudaFuncSetAttribute(gemm_tf32_multi<128, 1>, cudaFuncAttributeMaxDynamicSharedMemorySize, sm128);
    cudaFuncSetAttribute(gemm_tf32_multi<64, 3>, cudaFuncAttributeMaxDynamicSharedMemorySize, sm64);
    cudaFuncSetAttribute(gemm_tf32_multi<64, 1>, cudaFuncAttributeMaxDynamicSharedMemorySize, sm64);

    Scratch S;
    cudaGetSymbolAddress((void**)&S.rs_r_src, g_rs_r_src);
    cudaGetSymbolAddress((void**)&S.rs_r_dst, g_rs_r_dst);
    cudaGetSymbolAddress((void**)&S.rs_s_src, g_rs_s_src);
    cudaGetSymbolAddress((void**)&S.rs_s_dst, g_rs_s_dst);
    cudaGetSymbolAddress((void**)&S.hd_a, g_hd_a);
    cudaGetSymbolAddress((void**)&S.hd_b, g_hd_b);
    cudaGetSymbolAddress((void**)&S.hs_a, g_hs_a);
    cudaGetSymbolAddress((void**)&S.hs_b, g_hs_b);
    cudaGetSymbolAddress((void**)&S.y_rel, g_y_rel);
    cudaGetSymbolAddress((void**)&S.y_relby, g_y_relby);
    cudaGetSymbolAddress((void**)&S.y_sim, g_y_sim);
    cudaGetSymbolAddress((void**)&S.y_simby, g_y_simby);
    cudaGetSymbolAddress((void**)&S.cntA, g_cntA);
    cudaGetSymbolAddress((void**)&S.offA, g_offA);
    cudaGetSymbolAddress((void**)&S.curA, g_curA);
    cudaGetSymbolAddress((void**)&S.idxA, g_idxA);
    cudaGetSymbolAddress((void**)&S.cntB, g_cntB);
    cudaGetSymbolAddress((void**)&S.offB, g_offB);
    cudaGetSymbolAddress((void**)&S.curB, g_curB);
    cudaGetSymbolAddress((void**)&S.idxB, g_idxB);
    cudaGetSymbolAddress((void**)&S.cntC, g_cntC);
    cudaGetSymbolAddress((void**)&S.offC, g_offC);
    cudaGetSymbolAddress((void**)&S.curC, g_curC);
    cudaGetSymbolAddress((void**)&S.idxC, g_idxC);
    cudaGetSymbolAddress((void**)&S.cntD, g_cntD);
    cudaGetSymbolAddress((void**)&S.offD, g_offD);
    cudaGetSymbolAddress((void**)&S.curD, g_curD);
    cudaGetSymbolAddress((void**)&S.idxD, g_idxD);

    // --- CSR build + degrees ---
    zero_cnts<<<cdiv(NDRUG / 4, 256), 256>>>((int4*)S.cntA, (int4*)S.cntB,
                                             (int4*)S.cntC, (int4*)S.cntD);
    int Emax = Er > Es ? Er : Es;
    hist_kernel<<<cdiv(Emax, 256), 256>>>(rsrc, rdst, ssrc, sdst, Er, Es,
                                          S.cntA, S.cntB, S.cntC, S.cntD);
    scan4<<<4, 1024>>>(S.cntA, S.cntB, S.cntC, S.cntD,
                       S.offA, S.curA, S.rs_r_dst,
                       S.offB, S.curB, S.rs_r_src,
                       S.offC, S.curC, S.rs_s_dst,
                       S.offD, S.curD, S.rs_s_src);
    fill_all<<<cdiv(Emax, 256), 256>>>(rsrc, rdst, ssrc, sdst, Er, Es,
                                       S.curA, S.idxA, S.curB, S.idxB,
                                       S.curC, S.idxC, S.curD, S.idxD);

    // --- 3 layers ---
    run_layer<128>(S, embed_drug, embed_side, S.hd_a, S.hs_a, W1, b1, 1);
    run_layer<128>(S, S.hd_a, S.hs_a, S.hd_b, S.hs_b, W2, b2, 1);

    float* out = (float*)d_out;
    run_layer<64>(S, S.hd_b, S.hs_b, out, out + (long long)NDRUG * 64, W3, b3, 0);
}

// round 11
// speedup vs baseline: 1.0286x; 1.0286x over previous
#include <cuda_runtime.h>
#include <cstdint>

#define NDRUG 100000
#define NSIDE 5000
#define FDIM  128
#define EMAX  1000000

// ---------------------------------------------------------------------------
// Static device scratch
// ---------------------------------------------------------------------------
__device__ __align__(16) float g_rs_r_src[NDRUG];
__device__ __align__(16) float g_rs_r_dst[NSIDE];
__device__ __align__(16) float g_rs_s_src[NDRUG];
__device__ __align__(16) float g_rs_s_dst[NDRUG];

__device__ __align__(16) float g_hd_a[NDRUG * FDIM];
__device__ __align__(16) float g_hd_b[NDRUG * FDIM];
__device__ __align__(16) float g_hs_a[NSIDE * FDIM];
__device__ __align__(16) float g_hs_b[NSIDE * FDIM];

// Projected per-relation features, packed f16x2. Row = NOUT/2 words.
__device__ __align__(16) uint32_t g_y_rel[NDRUG * FDIM / 2];
__device__ __align__(16) uint32_t g_y_relby[NSIDE * FDIM / 2];
__device__ __align__(16) uint32_t g_y_sim[NDRUG * FDIM / 2];
__device__ __align__(16) uint32_t g_y_simby[NDRUG * FDIM / 2];

// CSR: A by relate_dst(side)<-relate_src ; B by relate_src(drug)<-relate_dst ;
//      C by sim_dst(drug)<-sim_src ; D by sim_src(drug)<-sim_dst
__device__ __align__(16) int g_cntA[NSIDE], g_offA[NSIDE], g_curA[NSIDE];
__device__ __align__(16) int g_cntB[NDRUG], g_offB[NDRUG], g_curB[NDRUG];
__device__ __align__(16) int g_cntC[NDRUG], g_offC[NDRUG], g_curC[NDRUG];
__device__ __align__(16) int g_cntD[NDRUG], g_offD[NDRUG], g_curD[NDRUG];
__device__ __align__(16) int g_idxA[EMAX], g_idxB[EMAX], g_idxC[EMAX], g_idxD[EMAX];

// ---------------------------------------------------------------------------
// f16x2 helpers via inline PTX
// ---------------------------------------------------------------------------
__device__ __forceinline__ uint32_t pack_h2(float lo, float hi) {
    uint32_t r;
    asm("cvt.rn.f16x2.f32 %0, %1, %2;" : "=r"(r) : "f"(hi), "f"(lo));
    return r;
}
__device__ __forceinline__ float2 unpack_h2(uint32_t v) {
    float2 f;
    asm("{ .reg .f16 lo, hi;\n\t"
        "  mov.b32 {lo, hi}, %2;\n\t"
        "  cvt.f32.f16 %0, lo;\n\t"
        "  cvt.f32.f16 %1, hi; }"
        : "=f"(f.x), "=f"(f.y) : "r"(v));
    return f;
}

// ---------------------------------------------------------------------------
// Utility kernels
// ---------------------------------------------------------------------------
__global__ void zero_cnts(int4* __restrict__ a, int4* __restrict__ b,
                          int4* __restrict__ c, int4* __restrict__ d) {
    int i = blockIdx.x * blockDim.x + threadIdx.x;
    int4 z = make_int4(0, 0, 0, 0);
    if (i < NSIDE / 4) a[i] = z;
    if (i < NDRUG / 4) { b[i] = z; c[i] = z; d[i] = z; }
}

__global__ void hist_kernel(const int* __restrict__ rsrc, const int* __restrict__ rdst,
                            const int* __restrict__ ssrc, const int* __restrict__ sdst,
                            int Er, int Es,
                            int* __restrict__ cA, int* __restrict__ cB,
                            int* __restrict__ cC, int* __restrict__ cD) {
    int e = blockIdx.x * blockDim.x + threadIdx.x;
    if (e < Er) {
        atomicAdd(&cA[rdst[e]], 1);
        atomicAdd(&cB[rsrc[e]], 1);
    }
    if (e < Es) {
        atomicAdd(&cC[sdst[e]], 1);
        atomicAdd(&cD[ssrc[e]], 1);
    }
}

__global__ void scan4(const int* __restrict__ cA, const int* __restrict__ cB,
                      const int* __restrict__ cC, const int* __restrict__ cD,
                      int* __restrict__ offA, int* __restrict__ curA, float* __restrict__ rsA,
                      int* __restrict__ offB, int* __restrict__ curB, float* __restrict__ rsB,
                      int* __restrict__ offC, int* __restrict__ curC, float* __restrict__ rsC,
                      int* __restrict__ offD, int* __restrict__ curD, float* __restrict__ rsD) {
    __shared__ int sm[1024];
    int b = blockIdx.x, tid = threadIdx.x;
    const int* cnt; int* off; int* cur; float* rs; int n;
    if (b == 0)      { cnt = cA; off = offA; cur = curA; rs = rsA; n = NSIDE; }
    else if (b == 1) { cnt = cB; off = offB; cur = curB; rs = rsB; n = NDRUG; }
    else if (b == 2) { cnt = cC; off = offC; cur = curC; rs = rsC; n = NDRUG; }
    else             { cnt = cD; off = offD; cur = curD; rs = rsD; n = NDRUG; }

    int chunk = (n + 1023) >> 10;
    int s0 = tid * chunk;
    int s1 = min(s0 + chunk, n);
    int s = 0;
    for (int i = s0; i < s1; ++i) s += cnt[i];
    sm[tid] = s;
    __syncthreads();
    for (int d = 1; d < 1024; d <<= 1) {
        int x = (tid >= d) ? sm[tid - d] : 0;
        __syncthreads();
        sm[tid] += x;
        __syncthreads();
    }
    int run = sm[tid] - s;  // exclusive prefix
    for (int i = s0; i < s1; ++i) {
        int c = cnt[i];
        off[i] = run;
        cur[i] = run;
        rs[i] = rsqrtf((float)(c > 0 ? c : 1));
        run += c;
    }
}

__global__ void fill_all(const int* __restrict__ rsrc, const int* __restrict__ rdst,
                         const int* __restrict__ ssrc, const int* __restrict__ sdst,
                         int Er, int Es,
                         int* __restrict__ curA, int* __restrict__ idxA,
                         int* __restrict__ curB, int* __restrict__ idxB,
                         int* __restrict__ curC, int* __restrict__ idxC,
                         int* __restrict__ curD, int* __restrict__ idxD) {
    int e = blockIdx.x * blockDim.x + threadIdx.x;
    if (e < Er) {
        int s = rsrc[e], d = rdst[e];
        idxA[atomicAdd(&curA[d], 1)] = s;
        idxB[atomicAdd(&curB[s], 1)] = d;
    }
    if (e < Es) {
        int s = ssrc[e], d = sdst[e];
        idxC[atomicAdd(&curC[d], 1)] = s;
        idxD[atomicAdd(&curD[s], 1)] = d;
    }
}

// ---------------------------------------------------------------------------
// tf32 tensor-core multi-relation GEMM, f16x2-packed output (round-9 proven).
// ---------------------------------------------------------------------------
__device__ __forceinline__ uint32_t f2tf(float f) {
    uint32_t r;
    asm("cvt.rna.tf32.f32 %0, %1;" : "=r"(r) : "f"(f));
    return r;
}
__device__ __forceinline__ void mma_tf32(float* d, const uint32_t* a, uint32_t b0, uint32_t b1) {
    asm("mma.sync.aligned.m16n8k8.row.col.f32.tf32.tf32.f32 "
        "{%0,%1,%2,%3}, {%4,%5,%6,%7}, {%8,%9}, {%0,%1,%2,%3};"
        : "+f"(d[0]), "+f"(d[1]), "+f"(d[2]), "+f"(d[3])
        : "r"(a[0]), "r"(a[1]), "r"(a[2]), "r"(a[3]), "r"(b0), "r"(b1));
}

template <int NOUT, int NREL>
__global__ __launch_bounds__(256) void gemm_tf32_multi(
    const float* __restrict__ X, int n,
    const float* __restrict__ W0, const float* __restrict__ W1, const float* __restrict__ W2,
    const float* __restrict__ rs0, const float* __restrict__ rs1, const float* __restrict__ rs2,
    uint32_t* __restrict__ Y0, uint32_t* __restrict__ Y1, uint32_t* __restrict__ Y2) {
    constexpr int XP = 132;
    constexpr int WP = NOUT + 8;
    constexpr int WN = NOUT / 4;
    constexpr int NT = WN / 8;
    constexpr int YW = NOUT / 2;

    extern __shared__ uint32_t smu[];
    uint32_t* Xs = smu;            // 64 * XP
    uint32_t* Ws = smu + 64 * XP;  // 128 * WP

    const int tid = threadIdx.x;
    const int row0 = blockIdx.x * 64;

    for (int i = tid; i < 64 * 32; i += 256) {
        int r = i >> 5, c4 = i & 31;
        int row = row0 + r;
        float4 v = make_float4(0.f, 0.f, 0.f, 0.f);
        if (row < n) v = reinterpret_cast<const float4*>(X)[row * 32 + c4];
        uint4 u = make_uint4(f2tf(v.x), f2tf(v.y), f2tf(v.z), f2tf(v.w));
        *reinterpret_cast<uint4*>(&Xs[r * XP + c4 * 4]) = u;
    }

    const int lane = tid & 31, wid = tid >> 5;
    const int g = lane >> 2, t = lane & 3;
    const int wm = wid & 1, wn = wid >> 1;
    const int nbase = wn * WN;
    const uint32_t* xbase = Xs + (wm * 32) * XP;

    #pragma unroll
    for (int rel = 0; rel < NREL; ++rel) {
        const float* W  = (rel == 0) ? W0  : (rel == 1) ? W1  : W2;
        const float* rs = (rel == 0) ? rs0 : (rel == 1) ? rs1 : rs2;
        uint32_t* Y     = (rel == 0) ? Y0  : (rel == 1) ? Y1  : Y2;

        __syncthreads();
        for (int i = tid; i < 128 * (NOUT / 4); i += 256) {
            int k = i / (NOUT / 4), c4 = i % (NOUT / 4);
            float4 v = reinterpret_cast<const float4*>(W)[i];
            uint4 u = make_uint4(f2tf(v.x), f2tf(v.y), f2tf(v.z), f2tf(v.w));
            *reinterpret_cast<uint4*>(&Ws[k * WP + c4 * 4]) = u;
        }
        __syncthreads();

        float acc[2][NT][4];
        #pragma unroll
        for (int mi = 0; mi < 2; ++mi)
            #pragma unroll
            for (int ni = 0; ni < NT; ++ni)
                #pragma unroll
                for (int j = 0; j < 4; ++j) acc[mi][ni][j] = 0.f;

        #pragma unroll
        for (int ks = 0; ks < 16; ++ks) {
            const int k0 = ks * 8;
            uint32_t a[2][4];
            #pragma unroll
            for (int mi = 0; mi < 2; ++mi) {
                const uint32_t* xb = xbase + mi * 16 * XP + k0;
                a[mi][0] = xb[g * XP + t];
                a[mi][1] = xb[(g + 8) * XP + t];
                a[mi][2] = xb[g * XP + t + 4];
                a[mi][3] = xb[(g + 8) * XP + t + 4];
            }
            #pragma unroll
            for (int ni = 0; ni < NT; ++ni) {
                uint32_t b0 = Ws[(k0 + t) * WP + nbase + ni * 8 + g];
                uint32_t b1 = Ws[(k0 + t + 4) * WP + nbase + ni * 8 + g];
                #pragma unroll
                for (int mi = 0; mi < 2; ++mi) mma_tf32(acc[mi][ni], a[mi], b0, b1);
            }
        }

        #pragma unroll
        for (int mi = 0; mi < 2; ++mi) {
            int r0 = row0 + wm * 32 + mi * 16 + g;
            float sa = (r0 < n) ? rs[r0] : 0.f;
            float sb = (r0 + 8 < n) ? rs[r0 + 8] : 0.f;
            #pragma unroll
            for (int ni = 0; ni < NT; ++ni) {
                int colw = (nbase + ni * 8 + 2 * t) >> 1;
                if (r0 < n)
                    Y[(long long)r0 * YW + colw] =
                        pack_h2(acc[mi][ni][0] * sa, acc[mi][ni][1] * sa);
                if (r0 + 8 < n)
                    Y[(long long)(r0 + 8) * YW + colw] =
                        pack_h2(acc[mi][ni][2] * sb, acc[mi][ni][3] * sb);
            }
        }
    }
}

// ---------------------------------------------------------------------------
// CSR gather. Side rows: round-9 proven loop. Drug rows: 3 relations
// INTERLEAVED in one loop (one chain, 3x natural MLP, single accumulator
// via per-relation fma scales).
// ---------------------------------------------------------------------------
__device__ __forceinline__ float4 segsum4h(const uint2* __restrict__ Y, int beg, int m,
                                           const int* __restrict__ idx, int lane) {
    float4 acc = make_float4(0.f, 0.f, 0.f, 0.f);
    for (int e0 = 0; e0 < m; e0 += 32) {
        int myi = (e0 + lane < m) ? idx[beg + e0 + lane] : 0;
        int lim = min(32, m - e0);
        #pragma unroll 4
        for (int j = 0; j < lim; ++j) {
            int s = __shfl_sync(0xffffffffu, myi, j);
            uint2 v = Y[s * 32 + lane];
            float2 f0 = unpack_h2(v.x);
            float2 f1 = unpack_h2(v.y);
            acc.x += f0.x; acc.y += f0.y; acc.z += f1.x; acc.w += f1.y;
        }
    }
    return acc;
}
__device__ __forceinline__ float2 segsum2h(const uint32_t* __restrict__ Y, int beg, int m,
                                           const int* __restrict__ idx, int lane) {
    float2 acc = make_float2(0.f, 0.f);
    for (int e0 = 0; e0 < m; e0 += 32) {
        int myi = (e0 + lane < m) ? idx[beg + e0 + lane] : 0;
        int lim = min(32, m - e0);
        #pragma unroll 4
        for (int j = 0; j < lim; ++j) {
            int s = __shfl_sync(0xffffffffu, myi, j);
            float2 f = unpack_h2(Y[s * 32 + lane]);
            acc.x += f.x; acc.y += f.y;
        }
    }
    return acc;
}

// Interleaved 3-stream drug segsum, NOUT=128 (uint2 rows).
__device__ __forceinline__ float4 segsum3_4h(
    const uint2* __restrict__ YB, int begB, int mB, const int* __restrict__ idxB, float s1,
    const uint2* __restrict__ YC, int begC, int mC, const int* __restrict__ idxC, float s2,
    const uint2* __restrict__ YD, int begD, int mD, const int* __restrict__ idxD, float s3,
    int lane) {
    float4 acc = make_float4(0.f, 0.f, 0.f, 0.f);
    int mmax = max(mB, max(mC, mD));
    for (int e0 = 0; e0 < mmax; e0 += 32) {
        int myB = (e0 + lane < mB) ? idxB[begB + e0 + lane] : 0;
        int myC = (e0 + lane < mC) ? idxC[begC + e0 + lane] : 0;
        int myD = (e0 + lane < mD) ? idxD[begD + e0 + lane] : 0;
        int lim = min(32, mmax - e0);
        for (int jb = 0; jb < lim; jb += 2) {
            uint2 vB[2], vC[2], vD[2];
            #pragma unroll
            for (int j = 0; j < 2; ++j) {
                int e = e0 + jb + j;
                int sB = __shfl_sync(0xffffffffu, myB, jb + j);
                int sC = __shfl_sync(0xffffffffu, myC, jb + j);
                int sD = __shfl_sync(0xffffffffu, myD, jb + j);
                vB[j] = (e < mB) ? YB[sB * 32 + lane] : make_uint2(0u, 0u);
                vC[j] = (e < mC) ? YC[sC * 32 + lane] : make_uint2(0u, 0u);
                vD[j] = (e < mD) ? YD[sD * 32 + lane] : make_uint2(0u, 0u);
            }
            #pragma unroll
            for (int j = 0; j < 2; ++j) {
                float2 f;
                f = unpack_h2(vB[j].x); acc.x = fmaf(f.x, s1, acc.x); acc.y = fmaf(f.y, s1, acc.y);
                f = unpack_h2(vB[j].y); acc.z = fmaf(f.x, s1, acc.z); acc.w = fmaf(f.y, s1, acc.w);
                f = unpack_h2(vC[j].x); acc.x = fmaf(f.x, s2, acc.x); acc.y = fmaf(f.y, s2, acc.y);
                f = unpack_h2(vC[j].y); acc.z = fmaf(f.x, s2, acc.z); acc.w = fmaf(f.y, s2, acc.w);
                f = unpack_h2(vD[j].x); acc.x = fmaf(f.x, s3, acc.x); acc.y = fmaf(f.y, s3, acc.y);
                f = unpack_h2(vD[j].y); acc.z = fmaf(f.x, s3, acc.z); acc.w = fmaf(f.y, s3, acc.w);
            }
        }
    }
    return acc;
}

// Interleaved 3-stream drug segsum, NOUT=64 (uint32 rows).
__device__ __forceinline__ float2 segsum3_2h(
    const uint32_t* __restrict__ YB, int begB, int mB, const int* __restrict__ idxB, float s1,
    const uint32_t* __restrict__ YC, int begC, int mC, const int* __restrict__ idxC, float s2,
    const uint32_t* __restrict__ YD, int begD, int mD, const int* __restrict__ idxD, float s3,
    int lane) {
    float2 acc = make_float2(0.f, 0.f);
    int mmax = max(mB, max(mC, mD));
    for (int e0 = 0; e0 < mmax; e0 += 32) {
        int myB = (e0 + lane < mB) ? idxB[begB + e0 + lane] : 0;
        int myC = (e0 + lane < mC) ? idxC[begC + e0 + lane] : 0;
        int myD = (e0 + lane < mD) ? idxD[begD + e0 + lane] : 0;
        int lim = min(32, mmax - e0);
        for (int jb = 0; jb < lim; jb += 2) {
            uint32_t vB[2], vC[2], vD[2];
            #pragma unroll
            for (int j = 0; j < 2; ++j) {
                int e = e0 + jb + j;
                int sB = __shfl_sync(0xffffffffu, myB, jb + j);
                int sC = __shfl_sync(0xffffffffu, myC, jb + j);
                int sD = __shfl_sync(0xffffffffu, myD, jb + j);
                vB[j] = (e < mB) ? YB[sB * 32 + lane] : 0u;
                vC[j] = (e < mC) ? YC[sC * 32 + lane] : 0u;
                vD[j] = (e < mD) ? YD[sD * 32 + lane] : 0u;
            }
            #pragma unroll
            for (int j = 0; j < 2; ++j) {
                float2 f;
                f = unpack_h2(vB[j]); acc.x = fmaf(f.x, s1, acc.x); acc.y = fmaf(f.y, s1, acc.y);
                f = unpack_h2(vC[j]); acc.x = fmaf(f.x, s2, acc.x); acc.y = fmaf(f.y, s2, acc.y);
                f = unpack_h2(vD[j]); acc.x = fmaf(f.x, s3, acc.x); acc.y = fmaf(f.y, s3, acc.y);
            }
        }
    }
    return acc;
}

template <int NOUT>
__global__ __launch_bounds__(256) void gather_all(
    const uint32_t* __restrict__ yA, const int* __restrict__ offA, const int* __restrict__ cntA,
    const int* __restrict__ idxA, const float* __restrict__ rsA,
    const uint32_t* __restrict__ yB, const int* __restrict__ offB, const int* __restrict__ cntB,
    const int* __restrict__ idxB, const float* __restrict__ rsB,
    const uint32_t* __restrict__ yC, const int* __restrict__ offC, const int* __restrict__ cntC,
    const int* __restrict__ idxC, const float* __restrict__ rsC,
    const uint32_t* __restrict__ yD, const int* __restrict__ offD, const int* __restrict__ cntD,
    const int* __restrict__ idxD, const float* __restrict__ rsD,
    const float* __restrict__ b, float* __restrict__ out_side, float* __restrict__ out_drug,
    int relu) {
    int w = (blockIdx.x * blockDim.x + threadIdx.x) >> 5;
    int lane = threadIdx.x & 31;

    if (w < NSIDE) {
        float s = rsA[w];
        if constexpr (NOUT == 128) {
            float4 a = segsum4h(reinterpret_cast<const uint2*>(yA), offA[w], cntA[w], idxA, lane);
            float4 bb = reinterpret_cast<const float4*>(b)[lane];
            float4 v = make_float4(fmaf(a.x, s, bb.x), fmaf(a.y, s, bb.y),
                                   fmaf(a.z, s, bb.z), fmaf(a.w, s, bb.w));
            if (relu) { v.x = fmaxf(v.x, 0.f); v.y = fmaxf(v.y, 0.f); v.z = fmaxf(v.z, 0.f); v.w = fmaxf(v.w, 0.f); }
            reinterpret_cast<float4*>(out_side)[w * 32 + lane] = v;
        } else {
            float2 a = segsum2h(yA, offA[w], cntA[w], idxA, lane);
            float2 bb = reinterpret_cast<const float2*>(b)[lane];
            float2 v = make_float2(fmaf(a.x, s, bb.x), fmaf(a.y, s, bb.y));
            if (relu) { v.x = fmaxf(v.x, 0.f); v.y = fmaxf(v.y, 0.f); }
            reinterpret_cast<float2*>(out_side)[w * 32 + lane] = v;
        }
        return;
    }
    int d = w - NSIDE;
    if (d >= NDRUG) return;
    float s1 = rsB[d], s2 = rsC[d], s3 = rsD[d];
    if constexpr (NOUT == 128) {
        float4 a = segsum3_4h(
            reinterpret_cast<const uint2*>(yB), offB[d], cntB[d], idxB, s1,
            reinterpret_cast<const uint2*>(yC), offC[d], cntC[d], idxC, s2,
            reinterpret_cast<const uint2*>(yD), offD[d], cntD[d], idxD, s3, lane);
        float4 b1 = reinterpret_cast<const float4*>(b)[1 * 32 + lane];
        float4 b2 = reinterpret_cast<const float4*>(b)[2 * 32 + lane];
        float4 b3 = reinterpret_cast<const float4*>(b)[3 * 32 + lane];
        float4 v;
        v.x = a.x + b1.x + b2.x + b3.x;
        v.y = a.y + b1.y + b2.y + b3.y;
        v.z = a.z + b1.z + b2.z + b3.z;
        v.w = a.w + b1.w + b2.w + b3.w;
        if (relu) { v.x = fmaxf(v.x, 0.f); v.y = fmaxf(v.y, 0.f); v.z = fmaxf(v.z, 0.f); v.w = fmaxf(v.w, 0.f); }
        reinterpret_cast<float4*>(out_drug)[d * 32 + lane] = v;
    } else {
        float2 a = segsum3_2h(
            yB, offB[d], cntB[d], idxB, s1,
            yC, offC[d], cntC[d], idxC, s2,
            yD, offD[d], cntD[d], idxD, s3, lane);
        float2 b1 = reinterpret_cast<const float2*>(b)[1 * 32 + lane];
        float2 b2 = reinterpret_cast<const float2*>(b)[2 * 32 + lane];
        float2 b3 = reinterpret_cast<const float2*>(b)[3 * 32 + lane];
        float2 v;
        v.x = a.x + b1.x + b2.x + b3.x;
        v.y = a.y + b1.y + b2.y + b3.y;
        if (relu) { v.x = fmaxf(v.x, 0.f); v.y = fmaxf(v.y, 0.f); }
        reinterpret_cast<float2*>(out_drug)[d * 32 + lane] = v;
    }
}

// ---------------------------------------------------------------------------
// Host side
// ---------------------------------------------------------------------------
struct Scratch {
    float *rs_r_src, *rs_r_dst, *rs_s_src, *rs_s_dst;
    float *hd_a, *hd_b, *hs_a, *hs_b;
    uint32_t *y_rel, *y_relby, *y_sim, *y_simby;
    int *cntA, *offA, *curA, *idxA;
    int *cntB, *offB, *curB, *idxB;
    int *cntC, *offC, *curC, *idxC;
    int *cntD, *offD, *curD, *idxD;
};

static inline int cdiv(long long a, long long b) { return (int)((a + b - 1) / b); }

template <int NOUT>
static void launch_gemms(const Scratch& S, const float* hd_in, const float* hs_in,
                         const float* W) {
    constexpr int XP = 132, WP = NOUT + 8;
    const int smem = (64 * XP + 128 * WP) * 4;
    const long long ws = 128LL * NOUT;
    gemm_tf32_multi<NOUT, 3><<<cdiv(NDRUG, 64), 256, smem>>>(
        hd_in, NDRUG,
        W + 0 * ws, W + 2 * ws, W + 3 * ws,
        S.rs_r_src, S.rs_s_src, S.rs_s_dst,
        S.y_rel, S.y_sim, S.y_simby);
    gemm_tf32_multi<NOUT, 1><<<cdiv(NSIDE, 64), 256, smem>>>(
        hs_in, NSIDE,
        W + 1 * ws, W + 1 * ws, W + 1 * ws,
        S.rs_r_dst, S.rs_r_dst, S.rs_r_dst,
        S.y_relby, S.y_relby, S.y_relby);
}

template <int NOUT>
static void launch_gather(const Scratch& S, float* hd_out, float* hs_out,
                          const float* b, int relu) {
    gather_all<NOUT><<<cdiv((NDRUG + NSIDE) * 32, 256), 256>>>(
        S.y_rel, S.offA, S.cntA, S.idxA, S.rs_r_dst,
        S.y_relby, S.offB, S.cntB, S.idxB, S.rs_r_src,
        S.y_sim,   S.offC, S.cntC, S.idxC, S.rs_s_dst,
        S.y_simby, S.offD, S.cntD, S.idxD, S.rs_s_src,
        b, hs_out, hd_out, relu);
}

extern "C" void kernel_launch(void* const* d_in, const int* in_sizes, int n_in,
                              void* d_out, int out_size) {
    const float* embed_drug = (const float*)d_in[0];
    const float* embed_side = (const float*)d_in[1];
    const int* rsrc = (const int*)d_in[2];
    const int* rdst = (const int*)d_in[3];
    const int* ssrc = (const int*)d_in[4];
    const int* sdst = (const int*)d_in[5];
    const float* W1 = (const float*)d_in[6];
    const float* b1 = (const float*)d_in[7];
    const float* W2 = (const float*)d_in[8];
    const float* b2 = (const float*)d_in[9];
    const float* W3 = (const float*)d_in[10];
    const float* b3 = (const float*)d_in[11];
    const int Er = in_sizes[2];
    const int Es = in_sizes[4];

    const int sm128 = (64 * 132 + 128 * 136) * 4;
    const int sm64  = (64 * 132 + 128 * 72) * 4;
    cudaFuncSetAttribute(gemm_tf32_multi<128, 3>, cudaFuncAttributeMaxDynamicSharedMemorySize, sm128);
    cudaFuncSetAttribute(gemm_tf32_multi<128, 1>, cudaFuncAttributeMaxDynamicSharedMemorySize, sm128);
    cudaFuncSetAttribute(gemm_tf32_multi<64, 3>, cudaFuncAttributeMaxDynamicSharedMemorySize, sm64);
    cudaFuncSetAttribute(gemm_tf32_multi<64, 1>, cudaFuncAttributeMaxDynamicSharedMemorySize, sm64);

    Scratch S;
    cudaGetSymbolAddress((void**)&S.rs_r_src, g_rs_r_src);
    cudaGetSymbolAddress((void**)&S.rs_r_dst, g_rs_r_dst);
    cudaGetSymbolAddress((void**)&S.rs_s_src, g_rs_s_src);
    cudaGetSymbolAddress((void**)&S.rs_s_dst, g_rs_s_dst);
    cudaGetSymbolAddress((void**)&S.hd_a, g_hd_a);
    cudaGetSymbolAddress((void**)&S.hd_b, g_hd_b);
    cudaGetSymbolAddress((void**)&S.hs_a, g_hs_a);
    cudaGetSymbolAddress((void**)&S.hs_b, g_hs_b);
    cudaGetSymbolAddress((void**)&S.y_rel, g_y_rel);
    cudaGetSymbolAddress((void**)&S.y_relby, g_y_relby);
    cudaGetSymbolAddress((void**)&S.y_sim, g_y_sim);
    cudaGetSymbolAddress((void**)&S.y_simby, g_y_simby);
    cudaGetSymbolAddress((void**)&S.cntA, g_cntA);
    cudaGetSymbolAddress((void**)&S.offA, g_offA);
    cudaGetSymbolAddress((void**)&S.curA, g_curA);
    cudaGetSymbolAddress((void**)&S.idxA, g_idxA);
    cudaGetSymbolAddress((void**)&S.cntB, g_cntB);
    cudaGetSymbolAddress((void**)&S.offB, g_offB);
    cudaGetSymbolAddress((void**)&S.curB, g_curB);
    cudaGetSymbolAddress((void**)&S.idxB, g_idxB);
    cudaGetSymbolAddress((void**)&S.cntC, g_cntC);
    cudaGetSymbolAddress((void**)&S.offC, g_offC);
    cudaGetSymbolAddress((void**)&S.curC, g_curC);
    cudaGetSymbolAddress((void**)&S.idxC, g_idxC);
    cudaGetSymbolAddress((void**)&S.cntD, g_cntD);
    cudaGetSymbolAddress((void**)&S.offD, g_offD);
    cudaGetSymbolAddress((void**)&S.curD, g_curD);
    cudaGetSymbolAddress((void**)&S.idxD, g_idxD);

    // --- CSR counts + scan (degrees) ---
    zero_cnts<<<cdiv(NDRUG / 4, 256), 256>>>((int4*)S.cntA, (int4*)S.cntB,
                                             (int4*)S.cntC, (int4*)S.cntD);
    int Emax = Er > Es ? Er : Es;
    hist_kernel<<<cdiv(Emax, 256), 256>>>(rsrc, rdst, ssrc, sdst, Er, Es,
                                          S.cntA, S.cntB, S.cntC, S.cntD);
    scan4<<<4, 1024>>>(S.cntA, S.cntB, S.cntC, S.cntD,
                       S.offA, S.curA, S.rs_r_dst,
                       S.offB, S.curB, S.rs_r_src,
                       S.offC, S.curC, S.rs_s_dst,
                       S.offD, S.curD, S.rs_s_src);

    // --- layer 1 GEMMs (need only rs, not idx) — fill_all overlaps here so
    //     the fixed ncu capture slot lands on the big GEMM next profile ---
    launch_gemms<128>(S, embed_drug, embed_side, W1);
    fill_all<<<cdiv(Emax, 256), 256>>>(rsrc, rdst, ssrc, sdst, Er, Es,
                                       S.curA, S.idxA, S.curB, S.idxB,
                                       S.curC, S.idxC, S.curD, S.idxD);
    launch_gather<128>(S, S.hd_a, S.hs_a, b1, 1);

    // --- layer 2 ---
    launch_gemms<128>(S, S.hd_a, S.hs_a, W2);
    launch_gather<128>(S, S.hd_b, S.hs_b, b2, 1);

    // --- layer 3 ---
    float* out = (float*)d_out;
    launch_gemms<64>(S, S.hd_b, S.hs_b, W3);
    launch_gather<64>(S, out, out + (long long)NDRUG * 64, b3, 0);
}

// round 14
// speedup vs baseline: 1.0674x; 1.0378x over previous
#include <cuda_runtime.h>
#include <cstdint>

#define NDRUG 100000
#define NSIDE 5000
#define FDIM  128
#define EMAX  1000000

// ---------------------------------------------------------------------------
// Static device scratch
// ---------------------------------------------------------------------------
__device__ __align__(16) float g_rs_r_src[NDRUG];
__device__ __align__(16) float g_rs_r_dst[NSIDE];
__device__ __align__(16) float g_rs_s_src[NDRUG];
__device__ __align__(16) float g_rs_s_dst[NDRUG];

__device__ __align__(16) float g_hd_a[NDRUG * FDIM];
__device__ __align__(16) float g_hd_b[NDRUG * FDIM];
__device__ __align__(16) float g_hs_a[NSIDE * FDIM];
__device__ __align__(16) float g_hs_b[NSIDE * FDIM];

// Projected per-relation features, packed f16x2. Row = NOUT/2 words.
__device__ __align__(16) uint32_t g_y_rel[NDRUG * FDIM / 2];
__device__ __align__(16) uint32_t g_y_relby[NSIDE * FDIM / 2];
__device__ __align__(16) uint32_t g_y_sim[NDRUG * FDIM / 2];
__device__ __align__(16) uint32_t g_y_simby[NDRUG * FDIM / 2];

// CSR: A by relate_dst(side)<-relate_src ; B by relate_src(drug)<-relate_dst ;
//      C by sim_dst(drug)<-sim_src ; D by sim_src(drug)<-sim_dst
__device__ __align__(16) int g_cntA[NSIDE], g_offA[NSIDE], g_curA[NSIDE];
__device__ __align__(16) int g_cntB[NDRUG], g_offB[NDRUG], g_curB[NDRUG];
__device__ __align__(16) int g_cntC[NDRUG], g_offC[NDRUG], g_curC[NDRUG];
__device__ __align__(16) int g_cntD[NDRUG], g_offD[NDRUG], g_curD[NDRUG];
__device__ __align__(16) int g_idxA[EMAX], g_idxB[EMAX], g_idxC[EMAX], g_idxD[EMAX];

// ---------------------------------------------------------------------------
// f16x2 helpers via inline PTX
// ---------------------------------------------------------------------------
__device__ __forceinline__ uint32_t pack_h2(float lo, float hi) {
    uint32_t r;
    asm("cvt.rn.f16x2.f32 %0, %1, %2;" : "=r"(r) : "f"(hi), "f"(lo));
    return r;
}
__device__ __forceinline__ float2 unpack_h2(uint32_t v) {
    float2 f;
    asm("{ .reg .f16 lo, hi;\n\t"
        "  mov.b32 {lo, hi}, %2;\n\t"
        "  cvt.f32.f16 %0, lo;\n\t"
        "  cvt.f32.f16 %1, hi; }"
        : "=f"(f.x), "=f"(f.y) : "r"(v));
    return f;
}

// ---------------------------------------------------------------------------
// Utility kernels
// ---------------------------------------------------------------------------
__global__ void zero_cnts(int4* __restrict__ a, int4* __restrict__ b,
                          int4* __restrict__ c, int4* __restrict__ d) {
    int i = blockIdx.x * blockDim.x + threadIdx.x;
    int4 z = make_int4(0, 0, 0, 0);
    if (i < NSIDE / 4) a[i] = z;
    if (i < NDRUG / 4) { b[i] = z; c[i] = z; d[i] = z; }
}

__global__ void hist_kernel(const int* __restrict__ rsrc, const int* __restrict__ rdst,
                            const int* __restrict__ ssrc, const int* __restrict__ sdst,
                            int Er, int Es,
                            int* __restrict__ cA, int* __restrict__ cB,
                            int* __restrict__ cC, int* __restrict__ cD) {
    int e = blockIdx.x * blockDim.x + threadIdx.x;
    if (e < Er) {
        atomicAdd(&cA[rdst[e]], 1);
        atomicAdd(&cB[rsrc[e]], 1);
    }
    if (e < Es) {
        atomicAdd(&cC[sdst[e]], 1);
        atomicAdd(&cD[ssrc[e]], 1);
    }
}

__global__ void scan4(const int* __restrict__ cA, const int* __restrict__ cB,
                      const int* __restrict__ cC, const int* __restrict__ cD,
                      int* __restrict__ offA, int* __restrict__ curA, float* __restrict__ rsA,
                      int* __restrict__ offB, int* __restrict__ curB, float* __restrict__ rsB,
                      int* __restrict__ offC, int* __restrict__ curC, float* __restrict__ rsC,
                      int* __restrict__ offD, int* __restrict__ curD, float* __restrict__ rsD) {
    __shared__ int sm[1024];
    int b = blockIdx.x, tid = threadIdx.x;
    const int* cnt; int* off; int* cur; float* rs; int n;
    if (b == 0)      { cnt = cA; off = offA; cur = curA; rs = rsA; n = NSIDE; }
    else if (b == 1) { cnt = cB; off = offB; cur = curB; rs = rsB; n = NDRUG; }
    else if (b == 2) { cnt = cC; off = offC; cur = curC; rs = rsC; n = NDRUG; }
    else             { cnt = cD; off = offD; cur = curD; rs = rsD; n = NDRUG; }

    int chunk = (n + 1023) >> 10;
    int s0 = tid * chunk;
    int s1 = min(s0 + chunk, n);
    int s = 0;
    for (int i = s0; i < s1; ++i) s += cnt[i];
    sm[tid] = s;
    __syncthreads();
    for (int d = 1; d < 1024; d <<= 1) {
        int x = (tid >= d) ? sm[tid - d] : 0;
        __syncthreads();
        sm[tid] += x;
        __syncthreads();
    }
    int run = sm[tid] - s;  // exclusive prefix
    for (int i = s0; i < s1; ++i) {
        int c = cnt[i];
        off[i] = run;
        cur[i] = run;
        rs[i] = rsqrtf((float)(c > 0 ? c : 1));
        run += c;
    }
}

__global__ void fill_all(const int* __restrict__ rsrc, const int* __restrict__ rdst,
                         const int* __restrict__ ssrc, const int* __restrict__ sdst,
                         int Er, int Es,
                         int* __restrict__ curA, int* __restrict__ idxA,
                         int* __restrict__ curB, int* __restrict__ idxB,
                         int* __restrict__ curC, int* __restrict__ idxC,
                         int* __restrict__ curD, int* __restrict__ idxD) {
    int e = blockIdx.x * blockDim.x + threadIdx.x;
    if (e < Er) {
        int s = rsrc[e], d = rdst[e];
        idxA[atomicAdd(&curA[d], 1)] = s;
        idxB[atomicAdd(&curB[s], 1)] = d;
    }
    if (e < Es) {
        int s = ssrc[e], d = sdst[e];
        idxC[atomicAdd(&curC[d], 1)] = s;
        idxD[atomicAdd(&curD[s], 1)] = d;
    }
}

// ---------------------------------------------------------------------------
// tf32 tensor-core multi-relation GEMM, f16x2-packed output.
// W staged in TWO K-halves (64 x WP smem) -> total smem 68.2KB -> 3 CTAs/SM.
// ---------------------------------------------------------------------------
__device__ __forceinline__ uint32_t f2tf(float f) {
    uint32_t r;
    asm("cvt.rna.tf32.f32 %0, %1;" : "=r"(r) : "f"(f));
    return r;
}
__device__ __forceinline__ void mma_tf32(float* d, const uint32_t* a, uint32_t b0, uint32_t b1) {
    asm("mma.sync.aligned.m16n8k8.row.col.f32.tf32.tf32.f32 "
        "{%0,%1,%2,%3}, {%4,%5,%6,%7}, {%8,%9}, {%0,%1,%2,%3};"
        : "+f"(d[0]), "+f"(d[1]), "+f"(d[2]), "+f"(d[3])
        : "r"(a[0]), "r"(a[1]), "r"(a[2]), "r"(a[3]), "r"(b0), "r"(b1));
}

template <int NOUT, int NREL>
__global__ __launch_bounds__(256) void gemm_tf32_multi(
    const float* __restrict__ X, int n,
    const float* __restrict__ W0, const float* __restrict__ W1, const float* __restrict__ W2,
    const float* __restrict__ rs0, const float* __restrict__ rs1, const float* __restrict__ rs2,
    uint32_t* __restrict__ Y0, uint32_t* __restrict__ Y1, uint32_t* __restrict__ Y2) {
    constexpr int XP = 132;
    constexpr int WP = NOUT + 8;
    constexpr int WN = NOUT / 4;
    constexpr int NT = WN / 8;
    constexpr int YW = NOUT / 2;

    extern __shared__ uint32_t smu[];
    uint32_t* Xs = smu;            // 64 * XP
    uint32_t* Ws = smu + 64 * XP;  // 64 * WP (one K-half of W)

    const int tid = threadIdx.x;
    const int row0 = blockIdx.x * 64;

    for (int i = tid; i < 64 * 32; i += 256) {
        int r = i >> 5, c4 = i & 31;
        int row = row0 + r;
        float4 v = make_float4(0.f, 0.f, 0.f, 0.f);
        if (row < n) v = reinterpret_cast<const float4*>(X)[row * 32 + c4];
        uint4 u = make_uint4(f2tf(v.x), f2tf(v.y), f2tf(v.z), f2tf(v.w));
        *reinterpret_cast<uint4*>(&Xs[r * XP + c4 * 4]) = u;
    }

    const int lane = tid & 31, wid = tid >> 5;
    const int g = lane >> 2, t = lane & 3;
    const int wm = wid & 1, wn = wid >> 1;
    const int nbase = wn * WN;
    const uint32_t* xbase = Xs + (wm * 32) * XP;

    #pragma unroll
    for (int rel = 0; rel < NREL; ++rel) {
        const float* W  = (rel == 0) ? W0  : (rel == 1) ? W1  : W2;
        const float* rs = (rel == 0) ? rs0 : (rel == 1) ? rs1 : rs2;
        uint32_t* Y     = (rel == 0) ? Y0  : (rel == 1) ? Y1  : Y2;

        float acc[2][NT][4];
        #pragma unroll
        for (int mi = 0; mi < 2; ++mi)
            #pragma unroll
            for (int ni = 0; ni < NT; ++ni)
                #pragma unroll
                for (int j = 0; j < 4; ++j) acc[mi][ni][j] = 0.f;

        for (int kh = 0; kh < 2; ++kh) {
            __syncthreads();   // protect Ws (and Xs on very first pass)
            // Stage K-half of W: rows [kh*64, kh*64+64)
            const float4* Wh = reinterpret_cast<const float4*>(W) + kh * 64 * (NOUT / 4);
            for (int i = tid; i < 64 * (NOUT / 4); i += 256) {
                int k = i / (NOUT / 4), c4 = i % (NOUT / 4);
                float4 v = Wh[i];
                uint4 u = make_uint4(f2tf(v.x), f2tf(v.y), f2tf(v.z), f2tf(v.w));
                *reinterpret_cast<uint4*>(&Ws[k * WP + c4 * 4]) = u;
            }
            __syncthreads();

            const uint32_t* xkh = xbase + kh * 64;
            #pragma unroll
            for (int ks = 0; ks < 8; ++ks) {
                const int k0 = ks * 8;
                uint32_t a[2][4];
                #pragma unroll
                for (int mi = 0; mi < 2; ++mi) {
                    const uint32_t* xb = xkh + mi * 16 * XP + k0;
                    a[mi][0] = xb[g * XP + t];
                    a[mi][1] = xb[(g + 8) * XP + t];
                    a[mi][2] = xb[g * XP + t + 4];
                    a[mi][3] = xb[(g + 8) * XP + t + 4];
                }
                #pragma unroll
                for (int ni = 0; ni < NT; ++ni) {
                    uint32_t b0 = Ws[(k0 + t) * WP + nbase + ni * 8 + g];
                    uint32_t b1 = Ws[(k0 + t + 4) * WP + nbase + ni * 8 + g];
                    #pragma unroll
                    for (int mi = 0; mi < 2; ++mi) mma_tf32(acc[mi][ni], a[mi], b0, b1);
                }
            }
        }

        #pragma unroll
        for (int mi = 0; mi < 2; ++mi) {
            int r0 = row0 + wm * 32 + mi * 16 + g;
            float sa = (r0 < n) ? rs[r0] : 0.f;
            float sb = (r0 + 8 < n) ? rs[r0 + 8] : 0.f;
            #pragma unroll
            for (int ni = 0; ni < NT; ++ni) {
                int colw = (nbase + ni * 8 + 2 * t) >> 1;
                if (r0 < n)
                    Y[(long long)r0 * YW + colw] =
                        pack_h2(acc[mi][ni][0] * sa, acc[mi][ni][1] * sa);
                if (r0 + 8 < n)
                    Y[(long long)(r0 + 8) * YW + colw] =
                        pack_h2(acc[mi][ni][2] * sb, acc[mi][ni][3] * sb);
            }
        }
    }
}

// ---------------------------------------------------------------------------
// Merged CSR gather over f16x2 Y (round-9 proven serial form).
// One warp per dst row; fp32 accumulation.
// ---------------------------------------------------------------------------
__device__ __forceinline__ float4 segsum4h(const uint2* __restrict__ Y, int beg, int m,
                                           const int* __restrict__ idx, int lane) {
    float4 acc = make_float4(0.f, 0.f, 0.f, 0.f);
    for (int e0 = 0; e0 < m; e0 += 32) {
        int myi = (e0 + lane < m) ? idx[beg + e0 + lane] : 0;
        int lim = min(32, m - e0);
        #pragma unroll 4
        for (int j = 0; j < lim; ++j) {
            int s = __shfl_sync(0xffffffffu, myi, j);
            uint2 v = Y[s * 32 + lane];
            float2 f0 = unpack_h2(v.x);
            float2 f1 = unpack_h2(v.y);
            acc.x += f0.x; acc.y += f0.y; acc.z += f1.x; acc.w += f1.y;
        }
    }
    return acc;
}
__device__ __forceinline__ float2 segsum2h(const uint32_t* __restrict__ Y, int beg, int m,
                                           const int* __restrict__ idx, int lane) {
    float2 acc = make_float2(0.f, 0.f);
    for (int e0 = 0; e0 < m; e0 += 32) {
        int myi = (e0 + lane < m) ? idx[beg + e0 + lane] : 0;
        int lim = min(32, m - e0);
        #pragma unroll 4
        for (int j = 0; j < lim; ++j) {
            int s = __shfl_sync(0xffffffffu, myi, j);
            float2 f = unpack_h2(Y[s * 32 + lane]);
            acc.x += f.x; acc.y += f.y;
        }
    }
    return acc;
}

template <int NOUT>
__global__ __launch_bounds__(256) void gather_all(
    const uint32_t* __restrict__ yA, const int* __restrict__ offA, const int* __restrict__ cntA,
    const int* __restrict__ idxA, const float* __restrict__ rsA,
    const uint32_t* __restrict__ yB, const int* __restrict__ offB, const int* __restrict__ cntB,
    const int* __restrict__ idxB, const float* __restrict__ rsB,
    const uint32_t* __restrict__ yC, const int* __restrict__ offC, const int* __restrict__ cntC,
    const int* __restrict__ idxC, const float* __restrict__ rsC,
    const uint32_t* __restrict__ yD, const int* __restrict__ offD, const int* __restrict__ cntD,
    const int* __restrict__ idxD, const float* __restrict__ rsD,
    const float* __restrict__ b, float* __restrict__ out_side, float* __restrict__ out_drug,
    int relu) {
    int w = (blockIdx.x * blockDim.x + threadIdx.x) >> 5;
    int lane = threadIdx.x & 31;

    if (w < NSIDE) {
        float s = rsA[w];
        if constexpr (NOUT == 128) {
            float4 a = segsum4h(reinterpret_cast<const uint2*>(yA), offA[w], cntA[w], idxA, lane);
            float4 bb = reinterpret_cast<const float4*>(b)[lane];
            float4 v = make_float4(fmaf(a.x, s, bb.x), fmaf(a.y, s, bb.y),
                                   fmaf(a.z, s, bb.z), fmaf(a.w, s, bb.w));
            if (relu) { v.x = fmaxf(v.x, 0.f); v.y = fmaxf(v.y, 0.f); v.z = fmaxf(v.z, 0.f); v.w = fmaxf(v.w, 0.f); }
            reinterpret_cast<float4*>(out_side)[w * 32 + lane] = v;
        } else {
            float2 a = segsum2h(yA, offA[w], cntA[w], idxA, lane);
            float2 bb = reinterpret_cast<const float2*>(b)[lane];
            float2 v = make_float2(fmaf(a.x, s, bb.x), fmaf(a.y, s, bb.y));
            if (relu) { v.x = fmaxf(v.x, 0.f); v.y = fmaxf(v.y, 0.f); }
            reinterpret_cast<float2*>(out_side)[w * 32 + lane] = v;
        }
        return;
    }
    int d = w - NSIDE;
    if (d >= NDRUG) return;
    float s1 = rsB[d], s2 = rsC[d], s3 = rsD[d];
    if constexpr (NOUT == 128) {
        float4 a1 = segsum4h(reinterpret_cast<const uint2*>(yB), offB[d], cntB[d], idxB, lane);
        float4 a2 = segsum4h(reinterpret_cast<const uint2*>(yC), offC[d], cntC[d], idxC, lane);
        float4 a3 = segsum4h(reinterpret_cast<const uint2*>(yD), offD[d], cntD[d], idxD, lane);
        float4 b1 = reinterpret_cast<const float4*>(b)[1 * 32 + lane];
        float4 b2 = reinterpret_cast<const float4*>(b)[2 * 32 + lane];
        float4 b3 = reinterpret_cast<const float4*>(b)[3 * 32 + lane];
        float4 v;
        v.x = fmaf(a1.x, s1, b1.x) + fmaf(a2.x, s2, b2.x) + fmaf(a3.x, s3, b3.x);
        v.y = fmaf(a1.y, s1, b1.y) + fmaf(a2.y, s2, b2.y) + fmaf(a3.y, s3, b3.y);
        v.z = fmaf(a1.z, s1, b1.z) + fmaf(a2.z, s2, b2.z) + fmaf(a3.z, s3, b3.z);
        v.w = fmaf(a1.w, s1, b1.w) + fmaf(a2.w, s2, b2.w) + fmaf(a3.w, s3, b3.w);
        if (relu) { v.x = fmaxf(v.x, 0.f); v.y = fmaxf(v.y, 0.f); v.z = fmaxf(v.z, 0.f); v.w = fmaxf(v.w, 0.f); }
        reinterpret_cast<float4*>(out_drug)[d * 32 + lane] = v;
    } else {
        float2 a1 = segsum2h(yB, offB[d], cntB[d], idxB, lane);
        float2 a2 = segsum2h(yC, offC[d], cntC[d], idxC, lane);
        float2 a3 = segsum2h(yD, offD[d], cntD[d], idxD, lane);
        float2 b1 = reinterpret_cast<const float2*>(b)[1 * 32 + lane];
        float2 b2 = reinterpret_cast<const float2*>(b)[2 * 32 + lane];
        float2 b3 = reinterpret_cast<const float2*>(b)[3 * 32 + lane];
        float2 v;
        v.x = fmaf(a1.x, s1, b1.x) + fmaf(a2.x, s2, b2.x) + fmaf(a3.x, s3, b3.x);
        v.y = fmaf(a1.y, s1, b1.y) + fmaf(a2.y, s2, b2.y) + fmaf(a3.y, s3, b3.y);
        if (relu) { v.x = fmaxf(v.x, 0.f); v.y = fmaxf(v.y, 0.f); }
        reinterpret_cast<float2*>(out_drug)[d * 32 + lane] = v;
    }
}

// ---------------------------------------------------------------------------
// Host side
// ---------------------------------------------------------------------------
struct Scratch {
    float *rs_r_src, *rs_r_dst, *rs_s_src, *rs_s_dst;
    float *hd_a, *hd_b, *hs_a, *hs_b;
    uint32_t *y_rel, *y_relby, *y_sim, *y_simby;
    int *cntA, *offA, *curA, *idxA;
    int *cntB, *offB, *curB, *idxB;
    int *cntC, *offC, *curC, *idxC;
    int *cntD, *offD, *curD, *idxD;
};

static inline int cdiv(long long a, long long b) { return (int)((a + b - 1) / b); }

template <int NOUT>
static void launch_gemms(const Scratch& S, const float* hd_in, const float* hs_in,
                         const float* W) {
    constexpr int XP = 132, WP = NOUT + 8;
    const int smem = (64 * XP + 64 * WP) * 4;
    const long long ws = 128LL * NOUT;
    gemm_tf32_multi<NOUT, 3><<<cdiv(NDRUG, 64), 256, smem>>>(
        hd_in, NDRUG,
        W + 0 * ws, W + 2 * ws, W + 3 * ws,
        S.rs_r_src, S.rs_s_src, S.rs_s_dst,
        S.y_rel, S.y_sim, S.y_simby);
    gemm_tf32_multi<NOUT, 1><<<cdiv(NSIDE, 64), 256, smem>>>(
        hs_in, NSIDE,
        W + 1 * ws, W + 1 * ws, W + 1 * ws,
        S.rs_r_dst, S.rs_r_dst, S.rs_r_dst,
        S.y_relby, S.y_relby, S.y_relby);
}

template <int NOUT>
static void launch_gather(const Scratch& S, float* hd_out, float* hs_out,
                          const float* b, int relu) {
    gather_all<NOUT><<<cdiv((NDRUG + NSIDE) * 32, 256), 256>>>(
        S.y_rel, S.offA, S.cntA, S.idxA, S.rs_r_dst,
        S.y_relby, S.offB, S.cntB, S.idxB, S.rs_r_src,
        S.y_sim,   S.offC, S.cntC, S.idxC, S.rs_s_dst,
        S.y_simby, S.offD, S.cntD, S.idxD, S.rs_s_src,
        b, hs_out, hd_out, relu);
}

extern "C" void kernel_launch(void* const* d_in, const int* in_sizes, int n_in,
                              void* d_out, int out_size) {
    const float* embed_drug = (const float*)d_in[0];
    const float* embed_side = (const float*)d_in[1];
    const int* rsrc = (const int*)d_in[2];
    const int* rdst = (const int*)d_in[3];
    const int* ssrc = (const int*)d_in[4];
    const int* sdst = (const int*)d_in[5];
    const float* W1 = (const float*)d_in[6];
    const float* b1 = (const float*)d_in[7];
    const float* W2 = (const float*)d_in[8];
    const float* b2 = (const float*)d_in[9];
    const float* W3 = (const float*)d_in[10];
    const float* b3 = (const float*)d_in[11];
    const int Er = in_sizes[2];
    const int Es = in_sizes[4];

    const int sm128 = (64 * 132 + 64 * 136) * 4;
    const int sm64  = (64 * 132 + 64 * 72) * 4;
    cudaFuncSetAttribute(gemm_tf32_multi<128, 3>, cudaFuncAttributeMaxDynamicSharedMemorySize, sm128);
    cudaFuncSetAttribute(gemm_tf32_multi<128, 1>, cudaFuncAttributeMaxDynamicSharedMemorySize, sm128);
    cudaFuncSetAttribute(gemm_tf32_multi<64, 3>, cudaFuncAttributeMaxDynamicSharedMemorySize, sm64);
    cudaFuncSetAttribute(gemm_tf32_multi<64, 1>, cudaFuncAttributeMaxDynamicSharedMemorySize, sm64);

    Scratch S;
    cudaGetSymbolAddress((void**)&S.rs_r_src, g_rs_r_src);
    cudaGetSymbolAddress((void**)&S.rs_r_dst, g_rs_r_dst);
    cudaGetSymbolAddress((void**)&S.rs_s_src, g_rs_s_src);
    cudaGetSymbolAddress((void**)&S.rs_s_dst, g_rs_s_dst);
    cudaGetSymbolAddress((void**)&S.hd_a, g_hd_a);
    cudaGetSymbolAddress((void**)&S.hd_b, g_hd_b);
    cudaGetSymbolAddress((void**)&S.hs_a, g_hs_a);
    cudaGetSymbolAddress((void**)&S.hs_b, g_hs_b);
    cudaGetSymbolAddress((void**)&S.y_rel, g_y_rel);
    cudaGetSymbolAddress((void**)&S.y_relby, g_y_relby);
    cudaGetSymbolAddress((void**)&S.y_sim, g_y_sim);
    cudaGetSymbolAddress((void**)&S.y_simby, g_y_simby);
    cudaGetSymbolAddress((void**)&S.cntA, g_cntA);
    cudaGetSymbolAddress((void**)&S.offA, g_offA);
    cudaGetSymbolAddress((void**)&S.curA, g_curA);
    cudaGetSymbolAddress((void**)&S.idxA, g_idxA);
    cudaGetSymbolAddress((void**)&S.cntB, g_cntB);
    cudaGetSymbolAddress((void**)&S.offB, g_offB);
    cudaGetSymbolAddress((void**)&S.curB, g_curB);
    cudaGetSymbolAddress((void**)&S.idxB, g_idxB);
    cudaGetSymbolAddress((void**)&S.cntC, g_cntC);
    cudaGetSymbolAddress((void**)&S.offC, g_offC);
    cudaGetSymbolAddress((void**)&S.curC, g_curC);
    cudaGetSymbolAddress((void**)&S.idxC, g_idxC);
    cudaGetSymbolAddress((void**)&S.cntD, g_cntD);
    cudaGetSymbolAddress((void**)&S.offD, g_offD);
    cudaGetSymbolAddress((void**)&S.curD, g_curD);
    cudaGetSymbolAddress((void**)&S.idxD, g_idxD);

    // --- CSR counts + scan (degrees) ---
    zero_cnts<<<cdiv(NDRUG / 4, 256), 256>>>((int4*)S.cntA, (int4*)S.cntB,
                                             (int4*)S.cntC, (int4*)S.cntD);
    int Emax = Er > Es ? Er : Es;
    hist_kernel<<<cdiv(Emax, 256), 256>>>(rsrc, rdst, ssrc, sdst, Er, Es,
                                          S.cntA, S.cntB, S.cntC, S.cntD);
    scan4<<<4, 1024>>>(S.cntA, S.cntB, S.cntC, S.cntD,
                       S.offA, S.curA, S.rs_r_dst,
                       S.offB, S.curB, S.rs_r_src,
                       S.offC, S.curC, S.rs_s_dst,
                       S.offD, S.curD, S.rs_s_src);

    // --- layer 1 GEMMs first (need only rs); fill_all overlaps, keeping the
    //     fixed ncu capture slot on gemm_tf32_multi<128,3> ---
    launch_gemms<128>(S, embed_drug, embed_side, W1);
    fill_all<<<cdiv(Emax, 256), 256>>>(rsrc, rdst, ssrc, sdst, Er, Es,
                                       S.curA, S.idxA, S.curB, S.idxB,
                                       S.curC, S.idxC, S.curD, S.idxD);
    launch_gather<128>(S, S.hd_a, S.hs_a, b1, 1);

    // --- layer 2 ---
    launch_gemms<128>(S, S.hd_a, S.hs_a, W2);
    launch_gather<128>(S, S.hd_b, S.hs_b, b2, 1);

    // --- layer 3 ---
    float* out = (float*)d_out;
    launch_gemms<64>(S, S.hd_b, S.hs_b, W3);
    launch_gather<64>(S, out, out + (long long)NDRUG * 64, b3, 0);
}

// round 16
// speedup vs baseline: 1.1839x; 1.1091x over previous
#include <cuda_runtime.h>
#include <cstdint>

#define NDRUG 100000
#define NSIDE 5000
#define FDIM  128
#define EMAX  1000000

// ---------------------------------------------------------------------------
// Static device scratch
// ---------------------------------------------------------------------------
__device__ __align__(16) float g_rs_r_src[NDRUG];
__device__ __align__(16) float g_rs_r_dst[NSIDE];
__device__ __align__(16) float g_rs_s_src[NDRUG];
__device__ __align__(16) float g_rs_s_dst[NDRUG];

__device__ __align__(16) float g_hd_a[NDRUG * FDIM];
__device__ __align__(16) float g_hd_b[NDRUG * FDIM];
__device__ __align__(16) float g_hs_a[NSIDE * FDIM];
__device__ __align__(16) float g_hs_b[NSIDE * FDIM];

// Projected per-relation features, packed f16x2. Row = NOUT/2 words.
__device__ __align__(16) uint32_t g_y_rel[NDRUG * FDIM / 2];
__device__ __align__(16) uint32_t g_y_relby[NSIDE * FDIM / 2];
__device__ __align__(16) uint32_t g_y_sim[NDRUG * FDIM / 2];
__device__ __align__(16) uint32_t g_y_simby[NDRUG * FDIM / 2];

// CSR: A by relate_dst(side)<-relate_src ; B by relate_src(drug)<-relate_dst ;
//      C by sim_dst(drug)<-sim_src ; D by sim_src(drug)<-sim_dst
__device__ __align__(16) int g_cntA[NSIDE], g_offA[NSIDE], g_curA[NSIDE];
__device__ __align__(16) int g_cntB[NDRUG], g_offB[NDRUG], g_curB[NDRUG];
__device__ __align__(16) int g_cntC[NDRUG], g_offC[NDRUG], g_curC[NDRUG];
__device__ __align__(16) int g_cntD[NDRUG], g_offD[NDRUG], g_curD[NDRUG];
__device__ __align__(16) int g_idxA[EMAX], g_idxB[EMAX], g_idxC[EMAX], g_idxD[EMAX];

// ---------------------------------------------------------------------------
// f16x2 helpers via inline PTX
// ---------------------------------------------------------------------------
__device__ __forceinline__ uint32_t pack_h2(float lo, float hi) {
    uint32_t r;
    asm("cvt.rn.f16x2.f32 %0, %1, %2;" : "=r"(r) : "f"(hi), "f"(lo));
    return r;
}
__device__ __forceinline__ float2 unpack_h2(uint32_t v) {
    float2 f;
    asm("{ .reg .f16 lo, hi;\n\t"
        "  mov.b32 {lo, hi}, %2;\n\t"
        "  cvt.f32.f16 %0, lo;\n\t"
        "  cvt.f32.f16 %1, hi; }"
        : "=f"(f.x), "=f"(f.y) : "r"(v));
    return f;
}

// ---------------------------------------------------------------------------
// Utility kernels
// ---------------------------------------------------------------------------
__global__ void zero_cnts(int4* __restrict__ a, int4* __restrict__ b,
                          int4* __restrict__ c, int4* __restrict__ d) {
    int i = blockIdx.x * blockDim.x + threadIdx.x;
    int4 z = make_int4(0, 0, 0, 0);
    if (i < NSIDE / 4) a[i] = z;
    if (i < NDRUG / 4) { b[i] = z; c[i] = z; d[i] = z; }
}

__global__ void hist_kernel(const int* __restrict__ rsrc, const int* __restrict__ rdst,
                            const int* __restrict__ ssrc, const int* __restrict__ sdst,
                            int Er, int Es,
                            int* __restrict__ cA, int* __restrict__ cB,
                            int* __restrict__ cC, int* __restrict__ cD) {
    int e = blockIdx.x * blockDim.x + threadIdx.x;
    if (e < Er) {
        atomicAdd(&cA[rdst[e]], 1);
        atomicAdd(&cB[rsrc[e]], 1);
    }
    if (e < Es) {
        atomicAdd(&cC[sdst[e]], 1);
        atomicAdd(&cD[ssrc[e]], 1);
    }
}

__global__ void scan4(const int* __restrict__ cA, const int* __restrict__ cB,
                      const int* __restrict__ cC, const int* __restrict__ cD,
                      int* __restrict__ offA, int* __restrict__ curA, float* __restrict__ rsA,
                      int* __restrict__ offB, int* __restrict__ curB, float* __restrict__ rsB,
                      int* __restrict__ offC, int* __restrict__ curC, float* __restrict__ rsC,
                      int* __restrict__ offD, int* __restrict__ curD, float* __restrict__ rsD) {
    __shared__ int sm[1024];
    int b = blockIdx.x, tid = threadIdx.x;
    const int* cnt; int* off; int* cur; float* rs; int n;
    if (b == 0)      { cnt = cA; off = offA; cur = curA; rs = rsA; n = NSIDE; }
    else if (b == 1) { cnt = cB; off = offB; cur = curB; rs = rsB; n = NDRUG; }
    else if (b == 2) { cnt = cC; off = offC; cur = curC; rs = rsC; n = NDRUG; }
    else             { cnt = cD; off = offD; cur = curD; rs = rsD; n = NDRUG; }

    int chunk = (n + 1023) >> 10;
    int s0 = tid * chunk;
    int s1 = min(s0 + chunk, n);
    int s = 0;
    for (int i = s0; i < s1; ++i) s += cnt[i];
    sm[tid] = s;
    __syncthreads();
    for (int d = 1; d < 1024; d <<= 1) {
        int x = (tid >= d) ? sm[tid - d] : 0;
        __syncthreads();
        sm[tid] += x;
        __syncthreads();
    }
    int run = sm[tid] - s;  // exclusive prefix
    for (int i = s0; i < s1; ++i) {
        int c = cnt[i];
        off[i] = run;
        cur[i] = run;
        rs[i] = rsqrtf((float)(c > 0 ? c : 1));
        run += c;
    }
}

__global__ void fill_all(const int* __restrict__ rsrc, const int* __restrict__ rdst,
                         const int* __restrict__ ssrc, const int* __restrict__ sdst,
                         int Er, int Es,
                         int* __restrict__ curA, int* __restrict__ idxA,
                         int* __restrict__ curB, int* __restrict__ idxB,
                         int* __restrict__ curC, int* __restrict__ idxC,
                         int* __restrict__ curD, int* __restrict__ idxD) {
    int e = blockIdx.x * blockDim.x + threadIdx.x;
    if (e < Er) {
        int s = rsrc[e], d = rdst[e];
        idxA[atomicAdd(&curA[d], 1)] = s;
        idxB[atomicAdd(&curB[s], 1)] = d;
    }
    if (e < Es) {
        int s = ssrc[e], d = sdst[e];
        idxC[atomicAdd(&curC[d], 1)] = s;
        idxD[atomicAdd(&curD[s], 1)] = d;
    }
}

// ---------------------------------------------------------------------------
// fp16 tensor-core multi-relation GEMM (m16n8k16), f16x2-packed output.
// X and W staged as packed f16x2 -> half the smem bytes AND half the LDS/MMA
// instruction count vs tf32 m16n8k8. Full K resident: smem 52.2KB (NOUT=128).
// Precision: fp16 mantissa (11 bit) == tf32 mantissa; fp32 accumulate.
// ---------------------------------------------------------------------------
__device__ __forceinline__ void mma_h16(float* d, const uint32_t* a, uint32_t b0, uint32_t b1) {
    asm("mma.sync.aligned.m16n8k16.row.col.f32.f16.f16.f32 "
        "{%0,%1,%2,%3}, {%4,%5,%6,%7}, {%8,%9}, {%0,%1,%2,%3};"
        : "+f"(d[0]), "+f"(d[1]), "+f"(d[2]), "+f"(d[3])
        : "r"(a[0]), "r"(a[1]), "r"(a[2]), "r"(a[3]), "r"(b0), "r"(b1));
}

template <int NOUT, int NREL>
__global__ __launch_bounds__(256) void gemm_h16_multi(
    const float* __restrict__ X, int n,
    const float* __restrict__ W0, const float* __restrict__ W1, const float* __restrict__ W2,
    const float* __restrict__ rs0, const float* __restrict__ rs1, const float* __restrict__ rs2,
    uint32_t* __restrict__ Y0, uint32_t* __restrict__ Y1, uint32_t* __restrict__ Y2) {
    constexpr int XP = 68;          // Xs pitch in f16x2 words (64 + 4); 68%32==4 -> A conflict-free
    constexpr int WP = NOUT + 8;    // Ws pitch in words; %32==8 -> B conflict-free
    constexpr int WN = NOUT / 4;    // cols per warp
    constexpr int NT = WN / 8;      // n8-tiles per warp
    constexpr int YW = NOUT / 2;    // words per Y row
    constexpr int WC4 = NOUT / 4;   // float4s per W row

    extern __shared__ uint32_t smu[];
    uint32_t* Xs = smu;             // 64 * XP   (rows x k-pair words)
    uint32_t* Ws = smu + 64 * XP;   // 64 * WP   (k-pair rows x cols)

    const int tid = threadIdx.x;
    const int row0 = blockIdx.x * 64;

    // Stage X as f16x2 along K: row r, word w = k/2.
    for (int i = tid; i < 64 * 32; i += 256) {
        int r = i >> 5, c4 = i & 31;
        int row = row0 + r;
        float4 v = make_float4(0.f, 0.f, 0.f, 0.f);
        if (row < n) v = reinterpret_cast<const float4*>(X)[row * 32 + c4];
        Xs[r * XP + c4 * 2]     = pack_h2(v.x, v.y);
        Xs[r * XP + c4 * 2 + 1] = pack_h2(v.z, v.w);
    }

    const int lane = tid & 31, wid = tid >> 5;
    const int g = lane >> 2, t = lane & 3;
    const int wm = wid & 1, wn = wid >> 1;
    const int nbase = wn * WN;
    const uint32_t* xbase = Xs + (wm * 32) * XP;

    #pragma unroll
    for (int rel = 0; rel < NREL; ++rel) {
        const float* W  = (rel == 0) ? W0  : (rel == 1) ? W1  : W2;
        const float* rs = (rel == 0) ? rs0 : (rel == 1) ? rs1 : rs2;
        uint32_t* Y     = (rel == 0) ? Y0  : (rel == 1) ? Y1  : Y2;

        __syncthreads();   // protect Ws (and Xs on first pass)
        // Stage W packed along K: word [kp][n] = (W[2kp][n], W[2kp+1][n]).
        for (int i = tid; i < 64 * WC4; i += 256) {
            int kp = i / WC4, c4 = i % WC4;
            float4 v0 = reinterpret_cast<const float4*>(W)[(2 * kp) * WC4 + c4];
            float4 v1 = reinterpret_cast<const float4*>(W)[(2 * kp + 1) * WC4 + c4];
            uint32_t* wdst = &Ws[kp * WP + c4 * 4];
            wdst[0] = pack_h2(v0.x, v1.x);
            wdst[1] = pack_h2(v0.y, v1.y);
            wdst[2] = pack_h2(v0.z, v1.z);
            wdst[3] = pack_h2(v0.w, v1.w);
        }
        __syncthreads();

        float acc[2][NT][4];
        #pragma unroll
        for (int mi = 0; mi < 2; ++mi)
            #pragma unroll
            for (int ni = 0; ni < NT; ++ni)
                #pragma unroll
                for (int j = 0; j < 4; ++j) acc[mi][ni][j] = 0.f;

        #pragma unroll
        for (int ks = 0; ks < 8; ++ks) {          // 8 steps of k16
            const int w0 = ks * 8;                // k-pair word base
            uint32_t a[2][4];
            #pragma unroll
            for (int mi = 0; mi < 2; ++mi) {
                const uint32_t* xb = xbase + mi * 16 * XP + w0;
                a[mi][0] = xb[g * XP + t];            // A[g][2t..2t+1]
                a[mi][1] = xb[(g + 8) * XP + t];      // A[g+8][..]
                a[mi][2] = xb[g * XP + t + 4];        // A[g][2t+8..]
                a[mi][3] = xb[(g + 8) * XP + t + 4];  // A[g+8][..]
            }
            #pragma unroll
            for (int ni = 0; ni < NT; ++ni) {
                uint32_t b0 = Ws[(w0 + t) * WP + nbase + ni * 8 + g];
                uint32_t b1 = Ws[(w0 + t + 4) * WP + nbase + ni * 8 + g];
                #pragma unroll
                for (int mi = 0; mi < 2; ++mi) mma_h16(acc[mi][ni], a[mi], b0, b1);
            }
        }

        #pragma unroll
        for (int mi = 0; mi < 2; ++mi) {
            int r0 = row0 + wm * 32 + mi * 16 + g;
            float sa = (r0 < n) ? rs[r0] : 0.f;
            float sb = (r0 + 8 < n) ? rs[r0 + 8] : 0.f;
            #pragma unroll
            for (int ni = 0; ni < NT; ++ni) {
                int colw = (nbase + ni * 8 + 2 * t) >> 1;
                if (r0 < n)
                    Y[(long long)r0 * YW + colw] =
                        pack_h2(acc[mi][ni][0] * sa, acc[mi][ni][1] * sa);
                if (r0 + 8 < n)
                    Y[(long long)(r0 + 8) * YW + colw] =
                        pack_h2(acc[mi][ni][2] * sb, acc[mi][ni][3] * sb);
            }
        }
    }
}

// ---------------------------------------------------------------------------
// Merged CSR gather over f16x2 Y (round-9 proven serial form).
// One warp per dst row; fp32 accumulation.
// ---------------------------------------------------------------------------
__device__ __forceinline__ float4 segsum4h(const uint2* __restrict__ Y, int beg, int m,
                                           const int* __restrict__ idx, int lane) {
    float4 acc = make_float4(0.f, 0.f, 0.f, 0.f);
    for (int e0 = 0; e0 < m; e0 += 32) {
        int myi = (e0 + lane < m) ? idx[beg + e0 + lane] : 0;
        int lim = min(32, m - e0);
        #pragma unroll 4
        for (int j = 0; j < lim; ++j) {
            int s = __shfl_sync(0xffffffffu, myi, j);
            uint2 v = Y[s * 32 + lane];
            float2 f0 = unpack_h2(v.x);
            float2 f1 = unpack_h2(v.y);
            acc.x += f0.x; acc.y += f0.y; acc.z += f1.x; acc.w += f1.y;
        }
    }
    return acc;
}
__device__ __forceinline__ float2 segsum2h(const uint32_t* __restrict__ Y, int beg, int m,
                                           const int* __restrict__ idx, int lane) {
    float2 acc = make_float2(0.f, 0.f);
    for (int e0 = 0; e0 < m; e0 += 32) {
        int myi = (e0 + lane < m) ? idx[beg + e0 + lane] : 0;
        int lim = min(32, m - e0);
        #pragma unroll 4
        for (int j = 0; j < lim; ++j) {
            int s = __shfl_sync(0xffffffffu, myi, j);
            float2 f = unpack_h2(Y[s * 32 + lane]);
            acc.x += f.x; acc.y += f.y;
        }
    }
    return acc;
}

template <int NOUT>
__global__ __launch_bounds__(256) void gather_all(
    const uint32_t* __restrict__ yA, const int* __restrict__ offA, const int* __restrict__ cntA,
    const int* __restrict__ idxA, const float* __restrict__ rsA,
    const uint32_t* __restrict__ yB, const int* __restrict__ offB, const int* __restrict__ cntB,
    const int* __restrict__ idxB, const float* __restrict__ rsB,
    const uint32_t* __restrict__ yC, const int* __restrict__ offC, const int* __restrict__ cntC,
    const int* __restrict__ idxC, const float* __restrict__ rsC,
    const uint32_t* __restrict__ yD, const int* __restrict__ offD, const int* __restrict__ cntD,
    const int* __restrict__ idxD, const float* __restrict__ rsD,
    const float* __restrict__ b, float* __restrict__ out_side, float* __restrict__ out_drug,
    int relu) {
    int w = (blockIdx.x * blockDim.x + threadIdx.x) >> 5;
    int lane = threadIdx.x & 31;

    if (w < NSIDE) {
        float s = rsA[w];
        if constexpr (NOUT == 128) {
            float4 a = segsum4h(reinterpret_cast<const uint2*>(yA), offA[w], cntA[w], idxA, lane);
            float4 bb = reinterpret_cast<const float4*>(b)[lane];
            float4 v = make_float4(fmaf(a.x, s, bb.x), fmaf(a.y, s, bb.y),
                                   fmaf(a.z, s, bb.z), fmaf(a.w, s, bb.w));
            if (relu) { v.x = fmaxf(v.x, 0.f); v.y = fmaxf(v.y, 0.f); v.z = fmaxf(v.z, 0.f); v.w = fmaxf(v.w, 0.f); }
            reinterpret_cast<float4*>(out_side)[w * 32 + lane] = v;
        } else {
            float2 a = segsum2h(yA, offA[w], cntA[w], idxA, lane);
            float2 bb = reinterpret_cast<const float2*>(b)[lane];
            float2 v = make_float2(fmaf(a.x, s, bb.x), fmaf(a.y, s, bb.y));
            if (relu) { v.x = fmaxf(v.x, 0.f); v.y = fmaxf(v.y, 0.f); }
            reinterpret_cast<float2*>(out_side)[w * 32 + lane] = v;
        }
        return;
    }
    int d = w - NSIDE;
    if (d >= NDRUG) return;
    float s1 = rsB[d], s2 = rsC[d], s3 = rsD[d];
    if constexpr (NOUT == 128) {
        float4 a1 = segsum4h(reinterpret_cast<const uint2*>(yB), offB[d], cntB[d], idxB, lane);
        float4 a2 = segsum4h(reinterpret_cast<const uint2*>(yC), offC[d], cntC[d], idxC, lane);
        float4 a3 = segsum4h(reinterpret_cast<const uint2*>(yD), offD[d], cntD[d], idxD, lane);
        float4 b1 = reinterpret_cast<const float4*>(b)[1 * 32 + lane];
        float4 b2 = reinterpret_cast<const float4*>(b)[2 * 32 + lane];
        float4 b3 = reinterpret_cast<const float4*>(b)[3 * 32 + lane];
        float4 v;
        v.x = fmaf(a1.x, s1, b1.x) + fmaf(a2.x, s2, b2.x) + fmaf(a3.x, s3, b3.x);
        v.y = fmaf(a1.y, s1, b1.y) + fmaf(a2.y, s2, b2.y) + fmaf(a3.y, s3, b3.y);
        v.z = fmaf(a1.z, s1, b1.z) + fmaf(a2.z, s2, b2.z) + fmaf(a3.z, s3, b3.z);
        v.w = fmaf(a1.w, s1, b1.w) + fmaf(a2.w, s2, b2.w) + fmaf(a3.w, s3, b3.w);
        if (relu) { v.x = fmaxf(v.x, 0.f); v.y = fmaxf(v.y, 0.f); v.z = fmaxf(v.z, 0.f); v.w = fmaxf(v.w, 0.f); }
        reinterpret_cast<float4*>(out_drug)[d * 32 + lane] = v;
    } else {
        float2 a1 = segsum2h(yB, offB[d], cntB[d], idxB, lane);
        float2 a2 = segsum2h(yC, offC[d], cntC[d], idxC, lane);
        float2 a3 = segsum2h(yD, offD[d], cntD[d], idxD, lane);
        float2 b1 = reinterpret_cast<const float2*>(b)[1 * 32 + lane];
        float2 b2 = reinterpret_cast<const float2*>(b)[2 * 32 + lane];
        float2 b3 = reinterpret_cast<const float2*>(b)[3 * 32 + lane];
        float2 v;
        v.x = fmaf(a1.x, s1, b1.x) + fmaf(a2.x, s2, b2.x) + fmaf(a3.x, s3, b3.x);
        v.y = fmaf(a1.y, s1, b1.y) + fmaf(a2.y, s2, b2.y) + fmaf(a3.y, s3, b3.y);
        if (relu) { v.x = fmaxf(v.x, 0.f); v.y = fmaxf(v.y, 0.f); }
        reinterpret_cast<float2*>(out_drug)[d * 32 + lane] = v;
    }
}

// ---------------------------------------------------------------------------
// Host side
// ---------------------------------------------------------------------------
struct Scratch {
    float *rs_r_src, *rs_r_dst, *rs_s_src, *rs_s_dst;
    float *hd_a, *hd_b, *hs_a, *hs_b;
    uint32_t *y_rel, *y_relby, *y_sim, *y_simby;
    int *cntA, *offA, *curA, *idxA;
    int *cntB, *offB, *curB, *idxB;
    int *cntC, *offC, *curC, *idxC;
    int *cntD, *offD, *curD, *idxD;
};

static inline int cdiv(long long a, long long b) { return (int)((a + b - 1) / b); }

template <int NOUT>
static void launch_gemms(const Scratch& S, const float* hd_in, const float* hs_in,
                         const float* W) {
    constexpr int XP = 68, WP = NOUT + 8;
    const int smem = (64 * XP + 64 * WP) * 4;
    const long long ws = 128LL * NOUT;
    gemm_h16_multi<NOUT, 3><<<cdiv(NDRUG, 64), 256, smem>>>(
        hd_in, NDRUG,
        W + 0 * ws, W + 2 * ws, W + 3 * ws,
        S.rs_r_src, S.rs_s_src, S.rs_s_dst,
        S.y_rel, S.y_sim, S.y_simby);
    gemm_h16_multi<NOUT, 1><<<cdiv(NSIDE, 64), 256, smem>>>(
        hs_in, NSIDE,
        W + 1 * ws, W + 1 * ws, W + 1 * ws,
        S.rs_r_dst, S.rs_r_dst, S.rs_r_dst,
        S.y_relby, S.y_relby, S.y_relby);
}

template <int NOUT>
static void launch_gather(const Scratch& S, float* hd_out, float* hs_out,
                          const float* b, int relu) {
    gather_all<NOUT><<<cdiv((NDRUG + NSIDE) * 32, 256), 256>>>(
        S.y_rel, S.offA, S.cntA, S.idxA, S.rs_r_dst,
        S.y_relby, S.offB, S.cntB, S.idxB, S.rs_r_src,
        S.y_sim,   S.offC, S.cntC, S.idxC, S.rs_s_dst,
        S.y_simby, S.offD, S.cntD, S.idxD, S.rs_s_src,
        b, hs_out, hd_out, relu);
}

extern "C" void kernel_launch(void* const* d_in, const int* in_sizes, int n_in,
                              void* d_out, int out_size) {
    const float* embed_drug = (const float*)d_in[0];
    const float* embed_side = (const float*)d_in[1];
    const int* rsrc = (const int*)d_in[2];
    const int* rdst = (const int*)d_in[3];
    const int* ssrc = (const int*)d_in[4];
    const int* sdst = (const int*)d_in[5];
    const float* W1 = (const float*)d_in[6];
    const float* b1 = (const float*)d_in[7];
    const float* W2 = (const float*)d_in[8];
    const float* b2 = (const float*)d_in[9];
    const float* W3 = (const float*)d_in[10];
    const float* b3 = (const float*)d_in[11];
    const int Er = in_sizes[2];
    const int Es = in_sizes[4];

    const int sm128 = (64 * 68 + 64 * 136) * 4;
    const int sm64  = (64 * 68 + 64 * 72) * 4;
    cudaFuncSetAttribute(gemm_h16_multi<128, 3>, cudaFuncAttributeMaxDynamicSharedMemorySize, sm128);
    cudaFuncSetAttribute(gemm_h16_multi<128, 1>, cudaFuncAttributeMaxDynamicSharedMemorySize, sm128);
    cudaFuncSetAttribute(gemm_h16_multi<64, 3>, cudaFuncAttributeMaxDynamicSharedMemorySize, sm64);
    cudaFuncSetAttribute(gemm_h16_multi<64, 1>, cudaFuncAttributeMaxDynamicSharedMemorySize, sm64);

    Scratch S;
    cudaGetSymbolAddress((void**)&S.rs_r_src, g_rs_r_src);
    cudaGetSymbolAddress((void**)&S.rs_r_dst, g_rs_r_dst);
    cudaGetSymbolAddress((void**)&S.rs_s_src, g_rs_s_src);
    cudaGetSymbolAddress((void**)&S.rs_s_dst, g_rs_s_dst);
    cudaGetSymbolAddress((void**)&S.hd_a, g_hd_a);
    cudaGetSymbolAddress((void**)&S.hd_b, g_hd_b);
    cudaGetSymbolAddress((void**)&S.hs_a, g_hs_a);
    cudaGetSymbolAddress((void**)&S.hs_b, g_hs_b);
    cudaGetSymbolAddress((void**)&S.y_rel, g_y_rel);
    cudaGetSymbolAddress((void**)&S.y_relby, g_y_relby);
    cudaGetSymbolAddress((void**)&S.y_sim, g_y_sim);
    cudaGetSymbolAddress((void**)&S.y_simby, g_y_simby);
    cudaGetSymbolAddress((void**)&S.cntA, g_cntA);
    cudaGetSymbolAddress((void**)&S.offA, g_offA);
    cudaGetSymbolAddress((void**)&S.curA, g_curA);
    cudaGetSymbolAddress((void**)&S.idxA, g_idxA);
    cudaGetSymbolAddress((void**)&S.cntB, g_cntB);
    cudaGetSymbolAddress((void**)&S.offB, g_offB);
    cudaGetSymbolAddress((void**)&S.curB, g_curB);
    cudaGetSymbolAddress((void**)&S.idxB, g_idxB);
    cudaGetSymbolAddress((void**)&S.cntC, g_cntC);
    cudaGetSymbolAddress((void**)&S.offC, g_offC);
    cudaGetSymbolAddress((void**)&S.curC, g_curC);
    cudaGetSymbolAddress((void**)&S.idxC, g_idxC);
    cudaGetSymbolAddress((void**)&S.cntD, g_cntD);
    cudaGetSymbolAddress((void**)&S.offD, g_offD);
    cudaGetSymbolAddress((void**)&S.curD, g_curD);
    cudaGetSymbolAddress((void**)&S.idxD, g_idxD);

    // --- CSR counts + scan (degrees) ---
    zero_cnts<<<cdiv(NDRUG / 4, 256), 256>>>((int4*)S.cntA, (int4*)S.cntB,
                                             (int4*)S.cntC, (int4*)S.cntD);
    int Emax = Er > Es ? Er : Es;
    hist_kernel<<<cdiv(Emax, 256), 256>>>(rsrc, rdst, ssrc, sdst, Er, Es,
                                          S.cntA, S.cntB, S.cntC, S.cntD);
    scan4<<<4, 1024>>>(S.cntA, S.cntB, S.cntC, S.cntD,
                       S.offA, S.curA, S.rs_r_dst,
                       S.offB, S.curB, S.rs_r_src,
                       S.offC, S.curC, S.rs_s_dst,
                       S.offD, S.curD, S.rs_s_src);

    // --- layer 1 GEMMs first (need only rs); fill_all overlaps, keeping the
    //     fixed ncu capture slot on gemm_h16_multi<128,3> ---
    launch_gemms<128>(S, embed_drug, embed_side, W1);
    fill_all<<<cdiv(Emax, 256), 256>>>(rsrc, rdst, ssrc, sdst, Er, Es,
                                       S.curA, S.idxA, S.curB, S.idxB,
                                       S.curC, S.idxC, S.curD, S.idxD);
    launch_gather<128>(S, S.hd_a, S.hs_a, b1, 1);

    // --- layer 2 ---
    launch_gemms<128>(S, S.hd_a, S.hs_a, W2);
    launch_gather<128>(S, S.hd_b, S.hs_b, b2, 1);

    // --- layer 3 ---
    float* out = (float*)d_out;
    launch_gemms<64>(S, S.hd_b, S.hs_b, W3);
    launch_gather<64>(S, out, out + (long long)NDRUG * 64, b3, 0);
}